// round 9
// baseline (speedup 1.0000x reference)
#include <cuda_runtime.h>
#include <cuda_bf16.h>
#include <cstdint>

#define B_   4
#define S_   2048
#define H_   16
#define DK_  64
#define DM_  1024
#define M_   (B_*S_)          // 8192
#define NA_  ((size_t)M_*DM_) // 8M elems
#define NW_  ((size_t)DM_*DM_)// 1M elems

// ---------------- scratch (__device__ globals; no allocs) ------------------
__device__ __nv_bfloat16 g_xqh[NA_], g_xql[NA_];
__device__ __nv_bfloat16 g_xkh[NA_], g_xkl[NA_];
__device__ __nv_bfloat16 g_xvh[NA_], g_xvl[NA_];
__device__ __nv_bfloat16 g_wqh[NW_], g_wql[NW_];
__device__ __nv_bfloat16 g_wkh[NW_], g_wkl[NW_];
__device__ __nv_bfloat16 g_wvh[NW_], g_wvl[NW_];
__device__ __nv_bfloat16 g_woh[NW_], g_wol[NW_];
__device__ __nv_bfloat16 g_qh[NA_], g_ql[NA_];
__device__ __nv_bfloat16 g_kh[NA_], g_kl[NA_];
__device__ __nv_bfloat16 g_vh[NA_], g_vl[NA_];
__device__ __nv_bfloat16 g_ch[NA_], g_cl[NA_];

// ---------------- PTX helpers ----------------------------------------------
__device__ __forceinline__ uint32_t smem_u32(const void* p) {
    uint32_t a;
    asm("{ .reg .u64 t; cvta.to.shared.u64 t, %1; cvt.u32.u64 %0, t; }"
        : "=r"(a) : "l"(p));
    return a;
}
__device__ __forceinline__ void ldsm_x4(uint32_t& r0, uint32_t& r1,
                                        uint32_t& r2, uint32_t& r3, uint32_t a) {
    asm volatile("ldmatrix.sync.aligned.m8n8.x4.shared.b16 {%0,%1,%2,%3}, [%4];"
                 : "=r"(r0), "=r"(r1), "=r"(r2), "=r"(r3) : "r"(a));
}
__device__ __forceinline__ void ldsm_x4t(uint32_t& r0, uint32_t& r1,
                                         uint32_t& r2, uint32_t& r3, uint32_t a) {
    asm volatile("ldmatrix.sync.aligned.m8n8.x4.trans.shared.b16 {%0,%1,%2,%3}, [%4];"
                 : "=r"(r0), "=r"(r1), "=r"(r2), "=r"(r3) : "r"(a));
}
__device__ __forceinline__ void mma_bf16(float* c,
                                         const uint32_t* a,
                                         uint32_t b0, uint32_t b1) {
    asm volatile("mma.sync.aligned.m16n8k16.row.col.f32.bf16.bf16.f32 "
                 "{%0,%1,%2,%3}, {%4,%5,%6,%7}, {%8,%9}, {%0,%1,%2,%3};"
                 : "+f"(c[0]), "+f"(c[1]), "+f"(c[2]), "+f"(c[3])
                 : "r"(a[0]), "r"(a[1]), "r"(a[2]), "r"(a[3]), "r"(b0), "r"(b1));
}
#define CP16(dst, src) \
    asm volatile("cp.async.cg.shared.global [%0], [%1], 16;" \
                 :: "r"(dst), "l"(src) : "memory")
#define CP_COMMIT() asm volatile("cp.async.commit_group;" ::: "memory")
#define CP_WAIT0()  asm volatile("cp.async.wait_group 0;"  ::: "memory")

__device__ __forceinline__ uint32_t pack_bf16(float x, float y) {
    __nv_bfloat162 t = __floats2bfloat162_rn(x, y);
    return reinterpret_cast<uint32_t&>(t);
}
__device__ __forceinline__ void split2(float x, float y, uint32_t& hi, uint32_t& lo) {
    __nv_bfloat16 hx = __float2bfloat16(x);
    __nv_bfloat16 hy = __float2bfloat16(y);
    __nv_bfloat162 h; h.x = hx; h.y = hy;
    hi = reinterpret_cast<uint32_t&>(h);
    lo = pack_bf16(x - __bfloat162float(hx), y - __bfloat162float(hy));
}

// ---------------- prep: fp32 -> bf16 hi/lo planes (batched up to 4) ---------
struct Prep4 { const float* x[4]; __nv_bfloat16* h[4]; __nv_bfloat16* l[4]; int n4; };

__global__ __launch_bounds__(256)
void prep_batch(Prep4 pa)
{
    const int z = blockIdx.y;
    const int i = blockIdx.x * 256 + threadIdx.x;
    if (i >= pa.n4) return;
    const float4 v = __ldg((const float4*)pa.x[z] + i);
    uint32_t h0, l0, h1, l1;
    split2(v.x, v.y, h0, l0);
    split2(v.z, v.w, h1, l1);
    ((uint2*)pa.h[z])[i] = make_uint2(h0, h1);
    ((uint2*)pa.l[z])[i] = make_uint2(l0, l1);
}

// ===========================================================================
// GEMM: C[M,N] = A[M,K]*W[N,K]^T + bias   (bf16 hi/lo, 3-term mma)
// CTA 128x128, K-tile 32, 2-stage cp.async double buffer, 80B rows,
// 2 CTAs/SM. MMAs round-robin over 4 live accumulators (RAW distance 4).
// ===========================================================================
#define GP2    (128*80)        // plane bytes 10240
#define GSTG2  (4*GP2)         // 40960
#define GSMEM2 (2*GSTG2)       // 81920
#define GKT2   (DM_/32)        // 32

struct GemmArgs {
    const __nv_bfloat16 *Ah, *Al, *Wh, *Wl;
    const float* bias;
    float scale;
    float* Cf;
    __nv_bfloat16 *Ch, *Cl;
};
struct GemmArgs3 { GemmArgs g[3]; };

template<bool SPLITO>
__global__ __launch_bounds__(256, 2)
void gemm_bf(GemmArgs3 aa)
{
    const GemmArgs ga = aa.g[blockIdx.z];
    extern __shared__ char smem[];
    const uint32_t sb = smem_u32(smem);
    const int tid = threadIdx.x;
    const int w = tid >> 5, l = tid & 31;
    const int wm = w & 3, wn = w >> 2;
    const int m0 = blockIdx.x * 128;
    const int n0 = blockIdx.y * 128;

    const int srow = tid >> 2;
    const int sch  = tid & 3;

    auto stage = [&](int kt, int s2) {
        const uint32_t buf = sb + (uint32_t)s2 * GSTG2;
        const int k0 = kt * 32;
        #pragma unroll
        for (int i = 0; i < 2; i++) {
            const int row = srow + i*64;
            const uint32_t off = (uint32_t)(row*80 + sch*16);
            CP16(buf + 0*GP2 + off, ga.Ah + (size_t)(m0+row)*DM_ + k0 + sch*8);
            CP16(buf + 1*GP2 + off, ga.Al + (size_t)(m0+row)*DM_ + k0 + sch*8);
            CP16(buf + 2*GP2 + off, ga.Wh + (size_t)(n0+row)*DM_ + k0 + sch*8);
            CP16(buf + 3*GP2 + off, ga.Wl + (size_t)(n0+row)*DM_ + k0 + sch*8);
        }
    };

    float acc[2][8][4];
    #pragma unroll
    for (int mt = 0; mt < 2; mt++)
        #pragma unroll
        for (int nt = 0; nt < 8; nt++)
            #pragma unroll
            for (int r = 0; r < 4; r++) acc[mt][nt][r] = 0.f;

    stage(0, 0); CP_COMMIT();

    const uint32_t a_row = (uint32_t)(wm*32 + (l & 15));
    const uint32_t a_kof = (uint32_t)(8 * (l >> 4));
    const uint32_t b4row = (uint32_t)(wn*64 + ((l >> 4) & 1)*8 + (l & 7));
    const uint32_t b_kof = (uint32_t)(8 * ((l >> 3) & 1));

    for (int kt = 0; kt < GKT2; kt++) {
        CP_WAIT0();
        __syncthreads();
        if (kt + 1 < GKT2) { stage(kt+1, (kt+1) & 1); CP_COMMIT(); }

        const uint32_t buf = sb + (uint32_t)((kt & 1) * GSTG2);
        #pragma unroll
        for (int ks = 0; ks < 2; ks++) {
            uint32_t ah[2][4], al[2][4];
            #pragma unroll
            for (int mt = 0; mt < 2; mt++) {
                const uint32_t ao = (a_row + mt*16)*80 + (ks*16 + a_kof)*2;
                ldsm_x4(ah[mt][0], ah[mt][1], ah[mt][2], ah[mt][3], buf + 0*GP2 + ao);
                ldsm_x4(al[mt][0], al[mt][1], al[mt][2], al[mt][3], buf + 1*GP2 + ao);
            }
            #pragma unroll
            for (int np = 0; np < 4; np++) {
                const uint32_t bo = (b4row + np*16)*80 + (ks*16 + b_kof)*2;
                uint32_t h0,h1,h2,h3, l0,l1,l2,l3;
                ldsm_x4(h0, h1, h2, h3, buf + 2*GP2 + bo);
                ldsm_x4(l0, l1, l2, l3, buf + 3*GP2 + bo);
                // round-robin over the 4 live accumulators (RAW distance 4)
                mma_bf16(acc[0][2*np  ], ah[0], h0, h1);
                mma_bf16(acc[1][2*np  ], ah[1], h0, h1);
                mma_bf16(acc[0][2*np+1], ah[0], h2, h3);
                mma_bf16(acc[1][2*np+1], ah[1], h2, h3);
                mma_bf16(acc[0][2*np  ], ah[0], l0, l1);
                mma_bf16(acc[1][2*np  ], ah[1], l0, l1);
                mma_bf16(acc[0][2*np+1], ah[0], l2, l3);
                mma_bf16(acc[1][2*np+1], ah[1], l2, l3);
                mma_bf16(acc[0][2*np  ], al[0], h0, h1);
                mma_bf16(acc[1][2*np  ], al[1], h0, h1);
                mma_bf16(acc[0][2*np+1], al[0], h2, h3);
                mma_bf16(acc[1][2*np+1], al[1], h2, h3);
            }
        }
    }

    // Epilogue
    #pragma unroll
    for (int mt = 0; mt < 2; mt++) {
        const int mrow = m0 + wm*32 + mt*16 + (l >> 2);
        #pragma unroll
        for (int nt = 0; nt < 8; nt++) {
            const int ncol = n0 + wn*64 + nt*8 + (l & 3)*2;
            const float2 bb = *(const float2*)(ga.bias + ncol);
            float2 o0 = { (acc[mt][nt][0] + bb.x)*ga.scale, (acc[mt][nt][1] + bb.y)*ga.scale };
            float2 o1 = { (acc[mt][nt][2] + bb.x)*ga.scale, (acc[mt][nt][3] + bb.y)*ga.scale };
            if (SPLITO) {
                const int h = ncol >> 6, d = ncol & 63;
                uint32_t hi, lo;
                const int b0i = mrow >> 11, s0i = mrow & (S_-1);
                size_t idx = ((size_t)((b0i*H_ + h)*S_ + s0i))*DK_ + d;
                split2(o0.x, o0.y, hi, lo);
                *(uint32_t*)(ga.Ch + idx) = hi;  *(uint32_t*)(ga.Cl + idx) = lo;
                const int m2 = mrow + 8;
                const int b1i = m2 >> 11, s1i = m2 & (S_-1);
                idx = ((size_t)((b1i*H_ + h)*S_ + s1i))*DK_ + d;
                split2(o1.x, o1.y, hi, lo);
                *(uint32_t*)(ga.Ch + idx) = hi;  *(uint32_t*)(ga.Cl + idx) = lo;
            } else {
                *(float2*)(ga.Cf + (size_t)mrow*DM_ + ncol) = o0;
                *(float2*)(ga.Cf + (size_t)(mrow+8)*DM_ + ncol) = o1;
            }
        }
    }
}

// ===========================================================================
// Flash attention: 64-query CTA, 8 warps (4m x 2n); wn splits the 64 keys.
// Each key-half warp runs a FULLY INDEPENDENT online softmax (own m,l,O);
// single exact merge at the end. 1 syncthreads per key block.
// ===========================================================================
#define AP_   (64*144)        // plane bytes 9216
#define ASTG  (4*AP_)         // 36864
#define ASMEM (2*ASTG)        // 73728
#define ANB   (S_/64)         // 32 key blocks

__global__ __launch_bounds__(256, 2)
void attn_mma_kernel()
{
    extern __shared__ char smem[];
    const uint32_t sb = smem_u32(smem);
    const int tid = threadIdx.x;
    const int w = tid >> 5, l = tid & 31;
    const int wm = w & 3, wn = w >> 2;
    const int q0 = blockIdx.x * 64;
    const int bh = blockIdx.y;

    const __nv_bfloat16* qph = g_qh + (size_t)bh*S_*DK_;
    const __nv_bfloat16* qpl = g_ql + (size_t)bh*S_*DK_;
    const __nv_bfloat16* kph = g_kh + (size_t)bh*S_*DK_;
    const __nv_bfloat16* kpl = g_kl + (size_t)bh*S_*DK_;
    const __nv_bfloat16* vph = g_vh + (size_t)bh*S_*DK_;
    const __nv_bfloat16* vpl = g_vl + (size_t)bh*S_*DK_;

    const int srow = tid >> 3;
    const int sch  = tid & 7;

    auto stage = [&](int j, int s2) {
        const uint32_t buf = sb + (uint32_t)s2 * ASTG;
        const int r0 = j*64;
        #pragma unroll
        for (int i = 0; i < 2; i++) {
            const int row = srow + i*32;
            const uint32_t off = (uint32_t)(row*144 + sch*16);
            const size_t g = (size_t)(r0+row)*DK_ + sch*8;
            CP16(buf + 0*AP_ + off, kph + g);
            CP16(buf + 1*AP_ + off, kpl + g);
            CP16(buf + 2*AP_ + off, vph + g);
            CP16(buf + 3*AP_ + off, vpl + g);
        }
    };

    stage(0, 0); CP_COMMIT();

    // Q fragments (pre-scaled in projection)
    uint32_t qh[4][4], ql[4][4];
    {
        const int r1 = q0 + wm*16 + (l >> 2);
        #pragma unroll
        for (int ks = 0; ks < 4; ks++) {
            #pragma unroll
            for (int rg = 0; rg < 4; rg++) {
                const int row = r1 + ((rg & 1) ? 8 : 0);
                const int col = ks*16 + (l & 3)*2 + ((rg & 2) ? 8 : 0);
                qh[ks][rg] = *(const uint32_t*)(qph + (size_t)row*DK_ + col);
                ql[ks][rg] = *(const uint32_t*)(qpl + (size_t)row*DK_ + col);
            }
        }
    }

    float o[8][4];
    #pragma unroll
    for (int t = 0; t < 8; t++)
        #pragma unroll
        for (int r = 0; r < 4; r++) o[t][r] = 0.f;
    float m1 = -1e30f, m2 = -1e30f, l1 = 0.f, l2 = 0.f;

    const uint32_t kqrow = (uint32_t)(wn*32 + ((l >> 4) & 1)*8 + (l & 7));
    const uint32_t kb_kof = (uint32_t)(8 * ((l >> 3) & 1));
    const uint32_t vrow_b = (uint32_t)(((l >> 3) & 1)*8 + (l & 7));
    const uint32_t vcol_b = (uint32_t)(((l >> 4) & 1)*8);

    for (int j = 0; j < ANB; j++) {
        CP_WAIT0();
        __syncthreads();
        if (j + 1 < ANB) { stage(j+1, (j+1) & 1); CP_COMMIT(); }

        const uint32_t buf = sb + (uint32_t)(j & 1) * ASTG;

        // S = Q K^T over this warp's 32 keys
        float s[4][4];
        #pragma unroll
        for (int t = 0; t < 4; t++)
            #pragma unroll
            for (int r = 0; r < 4; r++) s[t][r] = 0.f;

        #pragma unroll
        for (int ks = 0; ks < 4; ks++) {
            uint32_t kh2[2][4], kl2[2][4];
            #pragma unroll
            for (int tp = 0; tp < 2; tp++) {
                const uint32_t bo = (kqrow + tp*16)*144 + (ks*16 + kb_kof)*2;
                ldsm_x4(kh2[tp][0], kh2[tp][1], kh2[tp][2], kh2[tp][3], buf + 0*AP_ + bo);
                ldsm_x4(kl2[tp][0], kl2[tp][1], kl2[tp][2], kl2[tp][3], buf + 1*AP_ + bo);
            }
            // round-robin over the 4 s-accumulators (RAW distance 4)
            mma_bf16(s[0], qh[ks], kh2[0][0], kh2[0][1]);
            mma_bf16(s[1], qh[ks], kh2[0][2], kh2[0][3]);
            mma_bf16(s[2], qh[ks], kh2[1][0], kh2[1][1]);
            mma_bf16(s[3], qh[ks], kh2[1][2], kh2[1][3]);
            mma_bf16(s[0], qh[ks], kl2[0][0], kl2[0][1]);
            mma_bf16(s[1], qh[ks], kl2[0][2], kl2[0][3]);
            mma_bf16(s[2], qh[ks], kl2[1][0], kl2[1][1]);
            mma_bf16(s[3], qh[ks], kl2[1][2], kl2[1][3]);
            mma_bf16(s[0], ql[ks], kh2[0][0], kh2[0][1]);
            mma_bf16(s[1], ql[ks], kh2[0][2], kh2[0][3]);
            mma_bf16(s[2], ql[ks], kh2[1][0], kh2[1][1]);
            mma_bf16(s[3], ql[ks], kh2[1][2], kh2[1][3]);
        }

        // independent online softmax over this warp's key stream
        float rm1 = -1e30f, rm2 = -1e30f;
        #pragma unroll
        for (int t = 0; t < 4; t++) {
            rm1 = fmaxf(rm1, fmaxf(s[t][0], s[t][1]));
            rm2 = fmaxf(rm2, fmaxf(s[t][2], s[t][3]));
        }
        rm1 = fmaxf(rm1, __shfl_xor_sync(0xffffffffu, rm1, 1));
        rm1 = fmaxf(rm1, __shfl_xor_sync(0xffffffffu, rm1, 2));
        rm2 = fmaxf(rm2, __shfl_xor_sync(0xffffffffu, rm2, 1));
        rm2 = fmaxf(rm2, __shfl_xor_sync(0xffffffffu, rm2, 2));

        const float mn1 = fmaxf(m1, rm1), mn2 = fmaxf(m2, rm2);
        const float al1 = __expf(m1 - mn1), al2 = __expf(m2 - mn2);
        float sum1 = 0.f, sum2 = 0.f;
        #pragma unroll
        for (int t = 0; t < 4; t++) {
            s[t][0] = __expf(s[t][0] - mn1);
            s[t][1] = __expf(s[t][1] - mn1);
            s[t][2] = __expf(s[t][2] - mn2);
            s[t][3] = __expf(s[t][3] - mn2);
            sum1 += s[t][0] + s[t][1];
            sum2 += s[t][2] + s[t][3];
        }
        sum1 += __shfl_xor_sync(0xffffffffu, sum1, 1);
        sum1 += __shfl_xor_sync(0xffffffffu, sum1, 2);
        sum2 += __shfl_xor_sync(0xffffffffu, sum2, 1);
        sum2 += __shfl_xor_sync(0xffffffffu, sum2, 2);
        l1 = l1*al1 + sum1; l2 = l2*al2 + sum2;
        m1 = mn1; m2 = mn2;
        #pragma unroll
        for (int t = 0; t < 8; t++) {
            o[t][0] *= al1; o[t][1] *= al1;
            o[t][2] *= al2; o[t][3] *= al2;
        }

        // O += P @ V over this warp's keys (2 k16 steps)
        #pragma unroll
        for (int kss = 0; kss < 2; kss++) {
            const int ks_g = wn*2 + kss;
            uint32_t ph[4], pl[4];
            split2(s[2*kss  ][0], s[2*kss  ][1], ph[0], pl[0]);
            split2(s[2*kss  ][2], s[2*kss  ][3], ph[1], pl[1]);
            split2(s[2*kss+1][0], s[2*kss+1][1], ph[2], pl[2]);
            split2(s[2*kss+1][2], s[2*kss+1][3], ph[3], pl[3]);
            const uint32_t vrow = (uint32_t)(ks_g*16) + vrow_b;
            #pragma unroll
            for (int np = 0; np < 4; np++) {
                const uint32_t vo = vrow*144 + (np*16 + vcol_b)*2;
                uint32_t h0,h1,h2,h3, l0,l1_,l2,l3;
                ldsm_x4t(h0, h1, h2, h3, buf + 2*AP_ + vo);
                ldsm_x4t(l0, l1_, l2, l3, buf + 3*AP_ + vo);
                // distance-2 round robin over o[2np], o[2np+1]
                mma_bf16(o[2*np  ], ph, h0, h1);
                mma_bf16(o[2*np+1], ph, h2, h3);
                mma_bf16(o[2*np  ], ph, l0, l1_);
                mma_bf16(o[2*np+1], ph, l2, l3);
                mma_bf16(o[2*np  ], pl, h0, h1);
                mma_bf16(o[2*np+1], pl, h2, h3);
            }
        }
    }

    // -------- final merge of the two independent key-half streams ----------
    __syncthreads();
    float* comb = (float*)smem;          // O: 64 rows x 66 floats
    float* cm   = comb + 64*66;          // m per row
    float* clv  = cm + 64;               // l per row
    const int rl  = wm*16 + (l >> 2);
    const int cl2 = (l & 3)*2;
    if (wn == 1) {
        if ((l & 3) == 0) {
            cm[rl]     = m1;  cm[rl+8]  = m2;
            clv[rl]    = l1;  clv[rl+8] = l2;
        }
        #pragma unroll
        for (int t = 0; t < 8; t++) {
            *(float2*)&comb[ rl     *66 + t*8 + cl2] = make_float2(o[t][0], o[t][1]);
            *(float2*)&comb[(rl + 8)*66 + t*8 + cl2] = make_float2(o[t][2], o[t][3]);
        }
    }
    __syncthreads();
    if (wn == 0) {
        const float mB1 = cm[rl], mB2 = cm[rl+8];
        const float lB1 = clv[rl], lB2 = clv[rl+8];
        const float mw1 = fmaxf(m1, mB1), mw2 = fmaxf(m2, mB2);
        const float fs1 = __expf(m1 - mw1), fb1 = __expf(mB1 - mw1);
        const float fs2 = __expf(m2 - mw2), fb2 = __expf(mB2 - mw2);
        const float i1 = 1.f / (l1*fs1 + lB1*fb1);
        const float i2 = 1.f / (l2*fs2 + lB2*fb2);
        const int b = bh >> 4, h = bh & 15;
        const int row1 = q0 + rl;
        #pragma unroll
        for (int t = 0; t < 8; t++) {
            const float2 p0 = *(const float2*)&comb[ rl     *66 + t*8 + cl2];
            const float2 p1 = *(const float2*)&comb[(rl + 8)*66 + t*8 + cl2];
            const int col = h*DK_ + t*8 + cl2;
            uint32_t hi, lo;
            size_t idx = (size_t)(b*S_ + row1)*DM_ + col;
            split2((o[t][0]*fs1 + p0.x*fb1)*i1, (o[t][1]*fs1 + p0.y*fb1)*i1, hi, lo);
            *(uint32_t*)(g_ch + idx) = hi;  *(uint32_t*)(g_cl + idx) = lo;
            idx = (size_t)(b*S_ + row1 + 8)*DM_ + col;
            split2((o[t][2]*fs2 + p1.x*fb2)*i2, (o[t][3]*fs2 + p1.y*fb2)*i2, hi, lo);
            *(uint32_t*)(g_ch + idx) = hi;  *(uint32_t*)(g_cl + idx) = lo;
        }
    }
}

// ===========================================================================
extern "C" void kernel_launch(void* const* d_in, const int* in_sizes, int n_in,
                              void* d_out, int out_size)
{
    (void)in_sizes; (void)n_in; (void)out_size;
    const float* query = (const float*)d_in[0];
    const float* key   = (const float*)d_in[1];
    const float* value = (const float*)d_in[2];
    const float* Wq    = (const float*)d_in[3];
    const float* bq    = (const float*)d_in[4];
    const float* Wk    = (const float*)d_in[5];
    const float* bk    = (const float*)d_in[6];
    const float* Wv    = (const float*)d_in[7];
    const float* bv    = (const float*)d_in[8];
    const float* Wo    = (const float*)d_in[9];
    const float* bo    = (const float*)d_in[10];
    float* out = (float*)d_out;

    __nv_bfloat16 *xqh,*xql,*xkh,*xkl,*xvh,*xvl;
    __nv_bfloat16 *wqh,*wql,*wkh,*wkl,*wvh,*wvl,*woh,*wol;
    __nv_bfloat16 *qh,*ql_,*kh,*kl,*vh,*vl,*ch,*cl;
    cudaGetSymbolAddress((void**)&xqh, g_xqh); cudaGetSymbolAddress((void**)&xql, g_xql);
    cudaGetSymbolAddress((void**)&xkh, g_xkh); cudaGetSymbolAddress((void**)&xkl, g_xkl);
    cudaGetSymbolAddress((void**)&xvh, g_xvh); cudaGetSymbolAddress((void**)&xvl, g_xvl);
    cudaGetSymbolAddress((void**)&wqh, g_wqh); cudaGetSymbolAddress((void**)&wql, g_wql);
    cudaGetSymbolAddress((void**)&wkh, g_wkh); cudaGetSymbolAddress((void**)&wkl, g_wkl);
    cudaGetSymbolAddress((void**)&wvh, g_wvh); cudaGetSymbolAddress((void**)&wvl, g_wvl);
    cudaGetSymbolAddress((void**)&woh, g_woh); cudaGetSymbolAddress((void**)&wol, g_wol);
    cudaGetSymbolAddress((void**)&qh, g_qh);   cudaGetSymbolAddress((void**)&ql_, g_ql);
    cudaGetSymbolAddress((void**)&kh, g_kh);   cudaGetSymbolAddress((void**)&kl, g_kl);
    cudaGetSymbolAddress((void**)&vh, g_vh);   cudaGetSymbolAddress((void**)&vl, g_vl);
    cudaGetSymbolAddress((void**)&ch, g_ch);   cudaGetSymbolAddress((void**)&cl, g_cl);

    cudaFuncSetAttribute(gemm_bf<true>,
                         cudaFuncAttributeMaxDynamicSharedMemorySize, GSMEM2);
    cudaFuncSetAttribute(gemm_bf<false>,
                         cudaFuncAttributeMaxDynamicSharedMemorySize, GSMEM2);
    cudaFuncSetAttribute(attn_mma_kernel,
                         cudaFuncAttributeMaxDynamicSharedMemorySize, ASMEM);

    const int nA4 = (int)(NA_/4), nW4 = (int)(NW_/4);

    Prep4 pi; pi.n4 = nA4;
    pi.x[0]=query; pi.h[0]=xqh; pi.l[0]=xql;
    pi.x[1]=key;   pi.h[1]=xkh; pi.l[1]=xkl;
    pi.x[2]=value; pi.h[2]=xvh; pi.l[2]=xvl;
    pi.x[3]=query; pi.h[3]=xqh; pi.l[3]=xql;   // unused
    prep_batch<<<dim3((nA4+255)/256, 3), 256>>>(pi);

    Prep4 pw; pw.n4 = nW4;
    pw.x[0]=Wq; pw.h[0]=wqh; pw.l[0]=wql;
    pw.x[1]=Wk; pw.h[1]=wkh; pw.l[1]=wkl;
    pw.x[2]=Wv; pw.h[2]=wvh; pw.l[2]=wvl;
    pw.x[3]=Wo; pw.h[3]=woh; pw.l[3]=wol;
    prep_batch<<<dim3((nW4+255)/256, 4), 256>>>(pw);

    GemmArgs3 gq;
    gq.g[0] = { xqh, xql, wqh, wql, bq, 0.125f, nullptr, qh,  ql_ };
    gq.g[1] = { xkh, xkl, wkh, wkl, bk, 1.0f,   nullptr, kh,  kl  };
    gq.g[2] = { xvh, xvl, wvh, wvl, bv, 1.0f,   nullptr, vh,  vl  };
    gemm_bf<true><<<dim3(M_/128, DM_/128, 3), 256, GSMEM2>>>(gq);

    attn_mma_kernel<<<dim3(S_/64, B_*H_), 256, ASMEM>>>();

    GemmArgs3 go;
    go.g[0] = { ch, cl, woh, wol, bo, 1.0f, out, nullptr, nullptr };
    go.g[1] = go.g[0];
    go.g[2] = go.g[0];
    gemm_bf<false><<<dim3(M_/128, DM_/128, 1), 256, GSMEM2>>>(go);
}

// round 10
// speedup vs baseline: 1.0554x; 1.0554x over previous
#include <cuda_runtime.h>
#include <cuda_bf16.h>
#include <cstdint>

#define B_   4
#define S_   2048
#define H_   16
#define DK_  64
#define DM_  1024
#define M_   (B_*S_)          // 8192
#define NA_  ((size_t)M_*DM_) // 8M elems
#define NW_  ((size_t)DM_*DM_)// 1M elems

// ---------------- scratch (__device__ globals; no allocs) ------------------
__device__ __nv_bfloat16 g_xqh[NA_], g_xql[NA_];
__device__ __nv_bfloat16 g_xkh[NA_], g_xkl[NA_];
__device__ __nv_bfloat16 g_xvh[NA_], g_xvl[NA_];
__device__ __nv_bfloat16 g_wqh[NW_], g_wql[NW_];
__device__ __nv_bfloat16 g_wkh[NW_], g_wkl[NW_];
__device__ __nv_bfloat16 g_wvh[NW_], g_wvl[NW_];
__device__ __nv_bfloat16 g_woh[NW_], g_wol[NW_];
__device__ __nv_bfloat16 g_qh[NA_], g_ql[NA_];
__device__ __nv_bfloat16 g_kh[NA_], g_kl[NA_];
__device__ __nv_bfloat16 g_vh[NA_], g_vl[NA_];
__device__ __nv_bfloat16 g_ch[NA_], g_cl[NA_];

// ---------------- PTX helpers ----------------------------------------------
__device__ __forceinline__ uint32_t smem_u32(const void* p) {
    uint32_t a;
    asm("{ .reg .u64 t; cvta.to.shared.u64 t, %1; cvt.u32.u64 %0, t; }"
        : "=r"(a) : "l"(p));
    return a;
}
__device__ __forceinline__ void ldsm_x4(uint32_t& r0, uint32_t& r1,
                                        uint32_t& r2, uint32_t& r3, uint32_t a) {
    asm volatile("ldmatrix.sync.aligned.m8n8.x4.shared.b16 {%0,%1,%2,%3}, [%4];"
                 : "=r"(r0), "=r"(r1), "=r"(r2), "=r"(r3) : "r"(a));
}
__device__ __forceinline__ void ldsm_x4t(uint32_t& r0, uint32_t& r1,
                                         uint32_t& r2, uint32_t& r3, uint32_t a) {
    asm volatile("ldmatrix.sync.aligned.m8n8.x4.trans.shared.b16 {%0,%1,%2,%3}, [%4];"
                 : "=r"(r0), "=r"(r1), "=r"(r2), "=r"(r3) : "r"(a));
}
__device__ __forceinline__ void mma_bf16(float* c,
                                         const uint32_t* a,
                                         uint32_t b0, uint32_t b1) {
    asm volatile("mma.sync.aligned.m16n8k16.row.col.f32.bf16.bf16.f32 "
                 "{%0,%1,%2,%3}, {%4,%5,%6,%7}, {%8,%9}, {%0,%1,%2,%3};"
                 : "+f"(c[0]), "+f"(c[1]), "+f"(c[2]), "+f"(c[3])
                 : "r"(a[0]), "r"(a[1]), "r"(a[2]), "r"(a[3]), "r"(b0), "r"(b1));
}
#define CP16(dst, src) \
    asm volatile("cp.async.cg.shared.global [%0], [%1], 16;" \
                 :: "r"(dst), "l"(src) : "memory")
#define CP_COMMIT() asm volatile("cp.async.commit_group;" ::: "memory")
#define CP_WAIT1()  asm volatile("cp.async.wait_group 1;"  ::: "memory")

__device__ __forceinline__ uint32_t pack_bf16(float x, float y) {
    __nv_bfloat162 t = __floats2bfloat162_rn(x, y);
    return reinterpret_cast<uint32_t&>(t);
}
__device__ __forceinline__ void split2(float x, float y, uint32_t& hi, uint32_t& lo) {
    __nv_bfloat16 hx = __float2bfloat16(x);
    __nv_bfloat16 hy = __float2bfloat16(y);
    __nv_bfloat162 h; h.x = hx; h.y = hy;
    hi = reinterpret_cast<uint32_t&>(h);
    lo = pack_bf16(x - __bfloat162float(hx), y - __bfloat162float(hy));
}

// ---------------- prep: fp32 -> bf16 hi/lo planes (batched up to 4) ---------
struct Prep4 { const float* x[4]; __nv_bfloat16* h[4]; __nv_bfloat16* l[4]; int n4; };

__global__ __launch_bounds__(256)
void prep_batch(Prep4 pa)
{
    const int z = blockIdx.y;
    const int i = blockIdx.x * 256 + threadIdx.x;
    if (i >= pa.n4) return;
    const float4 v = __ldg((const float4*)pa.x[z] + i);
    uint32_t h0, l0, h1, l1;
    split2(v.x, v.y, h0, l0);
    split2(v.z, v.w, h1, l1);
    ((uint2*)pa.h[z])[i] = make_uint2(h0, h1);
    ((uint2*)pa.l[z])[i] = make_uint2(l0, l1);
}

// ===========================================================================
// GEMM: C[M,N] = A[M,K]*W[N,K]^T + bias   (bf16 hi/lo, 3-term mma)
// CTA 128x128, K-tile 32, 3-stage cp.async ring with wait_group 1.
// 64B rows with XOR swizzle (chunk ^= (row>>1)&3): 96 KB smem, 2 CTAs/SM.
// ===========================================================================
#define GP3    (128*64)        // plane bytes 8192
#define GSTG3  (4*GP3)         // 32768
#define GSMEM3 (3*GSTG3)       // 98304
#define GKT2   (DM_/32)        // 32

struct GemmArgs {
    const __nv_bfloat16 *Ah, *Al, *Wh, *Wl;
    const float* bias;
    float scale;
    float* Cf;
    __nv_bfloat16 *Ch, *Cl;
};
struct GemmArgs3 { GemmArgs g[3]; };

template<bool SPLITO>
__global__ __launch_bounds__(256, 2)
void gemm_bf(GemmArgs3 aa)
{
    const GemmArgs ga = aa.g[blockIdx.z];
    extern __shared__ char smem[];
    const uint32_t sb = smem_u32(smem);
    const int tid = threadIdx.x;
    const int w = tid >> 5, l = tid & 31;
    const int wm = w & 3, wn = w >> 2;
    const int m0 = blockIdx.x * 128;
    const int n0 = blockIdx.y * 128;

    // staging: each thread owns (row = tid>>2 [+64], chunk = tid&3)
    const int srow = tid >> 2;
    const int sch  = tid & 3;
    const uint32_t s_swz = (uint32_t)((srow >> 1) & 3);   // invariant for row+64
    const uint32_t s_off = (uint32_t)(((uint32_t)(sch) ^ s_swz) << 4);

    auto stage = [&](int kt, int s3) {
        const uint32_t buf = sb + (uint32_t)s3 * GSTG3;
        const int k0 = kt * 32;
        #pragma unroll
        for (int i = 0; i < 2; i++) {
            const int row = srow + i*64;
            const uint32_t off = (uint32_t)(row*64) + s_off;
            CP16(buf + 0*GP3 + off, ga.Ah + (size_t)(m0+row)*DM_ + k0 + sch*8);
            CP16(buf + 1*GP3 + off, ga.Al + (size_t)(m0+row)*DM_ + k0 + sch*8);
            CP16(buf + 2*GP3 + off, ga.Wh + (size_t)(n0+row)*DM_ + k0 + sch*8);
            CP16(buf + 3*GP3 + off, ga.Wl + (size_t)(n0+row)*DM_ + k0 + sch*8);
        }
    };

    float acc[2][8][4];
    #pragma unroll
    for (int mt = 0; mt < 2; mt++)
        #pragma unroll
        for (int nt = 0; nt < 8; nt++)
            #pragma unroll
            for (int r = 0; r < 4; r++) acc[mt][nt][r] = 0.f;

    stage(0, 0); CP_COMMIT();
    stage(1, 1); CP_COMMIT();

    // fragment addresses (swizzled; XOR terms are per-lane constants)
    const uint32_t a_row = (uint32_t)(wm*32 + (l & 15));
    const uint32_t a_ch0 = (uint32_t)(l >> 4);            // chunk for ks=0
    const uint32_t a_swz = (a_row >> 1) & 3;              // mt*16 invariant
    const uint32_t b4row = (uint32_t)(wn*64 + ((l >> 4) & 1)*8 + (l & 7));
    const uint32_t b_ch0 = (uint32_t)((l >> 3) & 1);
    const uint32_t b_swz = (b4row >> 1) & 3;              // np*16 invariant

    for (int kt = 0; kt < GKT2; kt++) {
        CP_WAIT1();
        __syncthreads();
        if (kt + 2 < GKT2) stage(kt+2, (kt+2)%3);
        CP_COMMIT();

        const uint32_t buf = sb + (uint32_t)((kt % 3) * GSTG3);
        #pragma unroll
        for (int ks = 0; ks < 2; ks++) {
            const uint32_t aoff = (((a_ch0 + ks*2) ^ a_swz) << 4);
            const uint32_t boff = (((b_ch0 + ks*2) ^ b_swz) << 4);
            uint32_t ah[2][4], al[2][4];
            #pragma unroll
            for (int mt = 0; mt < 2; mt++) {
                const uint32_t ao = (a_row + mt*16)*64 + aoff;
                ldsm_x4(ah[mt][0], ah[mt][1], ah[mt][2], ah[mt][3], buf + 0*GP3 + ao);
                ldsm_x4(al[mt][0], al[mt][1], al[mt][2], al[mt][3], buf + 1*GP3 + ao);
            }
            #pragma unroll
            for (int np = 0; np < 4; np++) {
                const uint32_t bo = (b4row + np*16)*64 + boff;
                uint32_t h0,h1,h2,h3, l0,l1,l2,l3;
                ldsm_x4(h0, h1, h2, h3, buf + 2*GP3 + bo);
                ldsm_x4(l0, l1, l2, l3, buf + 3*GP3 + bo);
                mma_bf16(acc[0][2*np  ], ah[0], h0, h1);
                mma_bf16(acc[1][2*np  ], ah[1], h0, h1);
                mma_bf16(acc[0][2*np+1], ah[0], h2, h3);
                mma_bf16(acc[1][2*np+1], ah[1], h2, h3);
                mma_bf16(acc[0][2*np  ], ah[0], l0, l1);
                mma_bf16(acc[1][2*np  ], ah[1], l0, l1);
                mma_bf16(acc[0][2*np+1], ah[0], l2, l3);
                mma_bf16(acc[1][2*np+1], ah[1], l2, l3);
                mma_bf16(acc[0][2*np  ], al[0], h0, h1);
                mma_bf16(acc[1][2*np  ], al[1], h0, h1);
                mma_bf16(acc[0][2*np+1], al[0], h2, h3);
                mma_bf16(acc[1][2*np+1], al[1], h2, h3);
            }
        }
    }

    // Epilogue
    #pragma unroll
    for (int mt = 0; mt < 2; mt++) {
        const int mrow = m0 + wm*32 + mt*16 + (l >> 2);
        #pragma unroll
        for (int nt = 0; nt < 8; nt++) {
            const int ncol = n0 + wn*64 + nt*8 + (l & 3)*2;
            const float2 bb = *(const float2*)(ga.bias + ncol);
            float2 o0 = { (acc[mt][nt][0] + bb.x)*ga.scale, (acc[mt][nt][1] + bb.y)*ga.scale };
            float2 o1 = { (acc[mt][nt][2] + bb.x)*ga.scale, (acc[mt][nt][3] + bb.y)*ga.scale };
            if (SPLITO) {
                const int h = ncol >> 6, d = ncol & 63;
                uint32_t hi, lo;
                const int b0i = mrow >> 11, s0i = mrow & (S_-1);
                size_t idx = ((size_t)((b0i*H_ + h)*S_ + s0i))*DK_ + d;
                split2(o0.x, o0.y, hi, lo);
                *(uint32_t*)(ga.Ch + idx) = hi;  *(uint32_t*)(ga.Cl + idx) = lo;
                const int m2 = mrow + 8;
                const int b1i = m2 >> 11, s1i = m2 & (S_-1);
                idx = ((size_t)((b1i*H_ + h)*S_ + s1i))*DK_ + d;
                split2(o1.x, o1.y, hi, lo);
                *(uint32_t*)(ga.Ch + idx) = hi;  *(uint32_t*)(ga.Cl + idx) = lo;
            } else {
                *(float2*)(ga.Cf + (size_t)mrow*DM_ + ncol) = o0;
                *(float2*)(ga.Cf + (size_t)(mrow+8)*DM_ + ncol) = o1;
            }
        }
    }
}

// ===========================================================================
// Flash attention: 64-query CTA, 8 warps (4m x 2n); wn splits the 64 keys.
// Independent per-half online softmax; single exact merge at the end.
// 3-stage cp.async ring with wait_group 1. 2 CTAs/SM.
// ===========================================================================
#define AP_   (64*144)        // plane bytes 9216
#define ASTG  (4*AP_)         // 36864
#define ASMEM (3*ASTG)        // 110592
#define ANB   (S_/64)         // 32 key blocks

__global__ __launch_bounds__(256, 2)
void attn_mma_kernel()
{
    extern __shared__ char smem[];
    const uint32_t sb = smem_u32(smem);
    const int tid = threadIdx.x;
    const int w = tid >> 5, l = tid & 31;
    const int wm = w & 3, wn = w >> 2;
    const int q0 = blockIdx.x * 64;
    const int bh = blockIdx.y;

    const __nv_bfloat16* qph = g_qh + (size_t)bh*S_*DK_;
    const __nv_bfloat16* qpl = g_ql + (size_t)bh*S_*DK_;
    const __nv_bfloat16* kph = g_kh + (size_t)bh*S_*DK_;
    const __nv_bfloat16* kpl = g_kl + (size_t)bh*S_*DK_;
    const __nv_bfloat16* vph = g_vh + (size_t)bh*S_*DK_;
    const __nv_bfloat16* vpl = g_vl + (size_t)bh*S_*DK_;

    const int srow = tid >> 3;
    const int sch  = tid & 7;

    auto stage = [&](int j, int s3) {
        const uint32_t buf = sb + (uint32_t)s3 * ASTG;
        const int r0 = j*64;
        #pragma unroll
        for (int i = 0; i < 2; i++) {
            const int row = srow + i*32;
            const uint32_t off = (uint32_t)(row*144 + sch*16);
            const size_t g = (size_t)(r0+row)*DK_ + sch*8;
            CP16(buf + 0*AP_ + off, kph + g);
            CP16(buf + 1*AP_ + off, kpl + g);
            CP16(buf + 2*AP_ + off, vph + g);
            CP16(buf + 3*AP_ + off, vpl + g);
        }
    };

    stage(0, 0); CP_COMMIT();
    stage(1, 1); CP_COMMIT();

    // Q fragments (pre-scaled in projection)
    uint32_t qh[4][4], ql[4][4];
    {
        const int r1 = q0 + wm*16 + (l >> 2);
        #pragma unroll
        for (int ks = 0; ks < 4; ks++) {
            #pragma unroll
            for (int rg = 0; rg < 4; rg++) {
                const int row = r1 + ((rg & 1) ? 8 : 0);
                const int col = ks*16 + (l & 3)*2 + ((rg & 2) ? 8 : 0);
                qh[ks][rg] = *(const uint32_t*)(qph + (size_t)row*DK_ + col);
                ql[ks][rg] = *(const uint32_t*)(qpl + (size_t)row*DK_ + col);
            }
        }
    }

    float o[8][4];
    #pragma unroll
    for (int t = 0; t < 8; t++)
        #pragma unroll
        for (int r = 0; r < 4; r++) o[t][r] = 0.f;
    float m1 = -1e30f, m2 = -1e30f, l1 = 0.f, l2 = 0.f;

    const uint32_t kqrow = (uint32_t)(wn*32 + ((l >> 4) & 1)*8 + (l & 7));
    const uint32_t kb_kof = (uint32_t)(8 * ((l >> 3) & 1));
    const uint32_t vrow_b = (uint32_t)(((l >> 3) & 1)*8 + (l & 7));
    const uint32_t vcol_b = (uint32_t)(((l >> 4) & 1)*8);

    for (int j = 0; j < ANB; j++) {
        CP_WAIT1();
        __syncthreads();
        if (j + 2 < ANB) stage(j+2, (j+2)%3);
        CP_COMMIT();

        const uint32_t buf = sb + (uint32_t)((j % 3) * ASTG);

        // S = Q K^T over this warp's 32 keys
        float s[4][4];
        #pragma unroll
        for (int t = 0; t < 4; t++)
            #pragma unroll
            for (int r = 0; r < 4; r++) s[t][r] = 0.f;

        #pragma unroll
        for (int ks = 0; ks < 4; ks++) {
            uint32_t kh2[2][4], kl2[2][4];
            #pragma unroll
            for (int tp = 0; tp < 2; tp++) {
                const uint32_t bo = (kqrow + tp*16)*144 + (ks*16 + kb_kof)*2;
                ldsm_x4(kh2[tp][0], kh2[tp][1], kh2[tp][2], kh2[tp][3], buf + 0*AP_ + bo);
                ldsm_x4(kl2[tp][0], kl2[tp][1], kl2[tp][2], kl2[tp][3], buf + 1*AP_ + bo);
            }
            mma_bf16(s[0], qh[ks], kh2[0][0], kh2[0][1]);
            mma_bf16(s[1], qh[ks], kh2[0][2], kh2[0][3]);
            mma_bf16(s[2], qh[ks], kh2[1][0], kh2[1][1]);
            mma_bf16(s[3], qh[ks], kh2[1][2], kh2[1][3]);
            mma_bf16(s[0], qh[ks], kl2[0][0], kl2[0][1]);
            mma_bf16(s[1], qh[ks], kl2[0][2], kl2[0][3]);
            mma_bf16(s[2], qh[ks], kl2[1][0], kl2[1][1]);
            mma_bf16(s[3], qh[ks], kl2[1][2], kl2[1][3]);
            mma_bf16(s[0], ql[ks], kh2[0][0], kh2[0][1]);
            mma_bf16(s[1], ql[ks], kh2[0][2], kh2[0][3]);
            mma_bf16(s[2], ql[ks], kh2[1][0], kh2[1][1]);
            mma_bf16(s[3], ql[ks], kh2[1][2], kh2[1][3]);
        }

        // independent online softmax over this warp's key stream
        float rm1 = -1e30f, rm2 = -1e30f;
        #pragma unroll
        for (int t = 0; t < 4; t++) {
            rm1 = fmaxf(rm1, fmaxf(s[t][0], s[t][1]));
            rm2 = fmaxf(rm2, fmaxf(s[t][2], s[t][3]));
        }
        rm1 = fmaxf(rm1, __shfl_xor_sync(0xffffffffu, rm1, 1));
        rm1 = fmaxf(rm1, __shfl_xor_sync(0xffffffffu, rm1, 2));
        rm2 = fmaxf(rm2, __shfl_xor_sync(0xffffffffu, rm2, 1));
        rm2 = fmaxf(rm2, __shfl_xor_sync(0xffffffffu, rm2, 2));

        const float mn1 = fmaxf(m1, rm1), mn2 = fmaxf(m2, rm2);
        const float al1 = __expf(m1 - mn1), al2 = __expf(m2 - mn2);
        float sum1 = 0.f, sum2 = 0.f;
        #pragma unroll
        for (int t = 0; t < 4; t++) {
            s[t][0] = __expf(s[t][0] - mn1);
            s[t][1] = __expf(s[t][1] - mn1);
            s[t][2] = __expf(s[t][2] - mn2);
            s[t][3] = __expf(s[t][3] - mn2);
            sum1 += s[t][0] + s[t][1];
            sum2 += s[t][2] + s[t][3];
        }
        sum1 += __shfl_xor_sync(0xffffffffu, sum1, 1);
        sum1 += __shfl_xor_sync(0xffffffffu, sum1, 2);
        sum2 += __shfl_xor_sync(0xffffffffu, sum2, 1);
        sum2 += __shfl_xor_sync(0xffffffffu, sum2, 2);
        l1 = l1*al1 + sum1; l2 = l2*al2 + sum2;
        m1 = mn1; m2 = mn2;
        #pragma unroll
        for (int t = 0; t < 8; t++) {
            o[t][0] *= al1; o[t][1] *= al1;
            o[t][2] *= al2; o[t][3] *= al2;
        }

        // O += P @ V over this warp's keys (2 k16 steps)
        #pragma unroll
        for (int kss = 0; kss < 2; kss++) {
            const int ks_g = wn*2 + kss;
            uint32_t ph[4], pl[4];
            split2(s[2*kss  ][0], s[2*kss  ][1], ph[0], pl[0]);
            split2(s[2*kss  ][2], s[2*kss  ][3], ph[1], pl[1]);
            split2(s[2*kss+1][0], s[2*kss+1][1], ph[2], pl[2]);
            split2(s[2*kss+1][2], s[2*kss+1][3], ph[3], pl[3]);
            const uint32_t vrow = (uint32_t)(ks_g*16) + vrow_b;
            #pragma unroll
            for (int np = 0; np < 4; np++) {
                const uint32_t vo = vrow*144 + (np*16 + vcol_b)*2;
                uint32_t h0,h1,h2,h3, l0,l1_,l2,l3;
                ldsm_x4t(h0, h1, h2, h3, buf + 2*AP_ + vo);
                ldsm_x4t(l0, l1_, l2, l3, buf + 3*AP_ + vo);
                mma_bf16(o[2*np  ], ph, h0, h1);
                mma_bf16(o[2*np+1], ph, h2, h3);
                mma_bf16(o[2*np  ], ph, l0, l1_);
                mma_bf16(o[2*np+1], ph, l2, l3);
                mma_bf16(o[2*np  ], pl, h0, h1);
                mma_bf16(o[2*np+1], pl, h2, h3);
            }
        }
    }

    // -------- final merge of the two independent key-half streams ----------
    __syncthreads();
    float* comb = (float*)smem;          // O: 64 rows x 66 floats
    float* cm   = comb + 64*66;          // m per row
    float* clv  = cm + 64;               // l per row
    const int rl  = wm*16 + (l >> 2);
    const int cl2 = (l & 3)*2;
    if (wn == 1) {
        if ((l & 3) == 0) {
            cm[rl]     = m1;  cm[rl+8]  = m2;
            clv[rl]    = l1;  clv[rl+8] = l2;
        }
        #pragma unroll
        for (int t = 0; t < 8; t++) {
            *(float2*)&comb[ rl     *66 + t*8 + cl2] = make_float2(o[t][0], o[t][1]);
            *(float2*)&comb[(rl + 8)*66 + t*8 + cl2] = make_float2(o[t][2], o[t][3]);
        }
    }
    __syncthreads();
    if (wn == 0) {
        const float mB1 = cm[rl], mB2 = cm[rl+8];
        const float lB1 = clv[rl], lB2 = clv[rl+8];
        const float mw1 = fmaxf(m1, mB1), mw2 = fmaxf(m2, mB2);
        const float fs1 = __expf(m1 - mw1), fb1 = __expf(mB1 - mw1);
        const float fs2 = __expf(m2 - mw2), fb2 = __expf(mB2 - mw2);
        const float i1 = 1.f / (l1*fs1 + lB1*fb1);
        const float i2 = 1.f / (l2*fs2 + lB2*fb2);
        const int b = bh >> 4, h = bh & 15;
        const int row1 = q0 + rl;
        #pragma unroll
        for (int t = 0; t < 8; t++) {
            const float2 p0 = *(const float2*)&comb[ rl     *66 + t*8 + cl2];
            const float2 p1 = *(const float2*)&comb[(rl + 8)*66 + t*8 + cl2];
            const int col = h*DK_ + t*8 + cl2;
            uint32_t hi, lo;
            size_t idx = (size_t)(b*S_ + row1)*DM_ + col;
            split2((o[t][0]*fs1 + p0.x*fb1)*i1, (o[t][1]*fs1 + p0.y*fb1)*i1, hi, lo);
            *(uint32_t*)(g_ch + idx) = hi;  *(uint32_t*)(g_cl + idx) = lo;
            idx = (size_t)(b*S_ + row1 + 8)*DM_ + col;
            split2((o[t][2]*fs2 + p1.x*fb2)*i2, (o[t][3]*fs2 + p1.y*fb2)*i2, hi, lo);
            *(uint32_t*)(g_ch + idx) = hi;  *(uint32_t*)(g_cl + idx) = lo;
        }
    }
}

// ===========================================================================
extern "C" void kernel_launch(void* const* d_in, const int* in_sizes, int n_in,
                              void* d_out, int out_size)
{
    (void)in_sizes; (void)n_in; (void)out_size;
    const float* query = (const float*)d_in[0];
    const float* key   = (const float*)d_in[1];
    const float* value = (const float*)d_in[2];
    const float* Wq    = (const float*)d_in[3];
    const float* bq    = (const float*)d_in[4];
    const float* Wk    = (const float*)d_in[5];
    const float* bk    = (const float*)d_in[6];
    const float* Wv    = (const float*)d_in[7];
    const float* bv    = (const float*)d_in[8];
    const float* Wo    = (const float*)d_in[9];
    const float* bo    = (const float*)d_in[10];
    float* out = (float*)d_out;

    __nv_bfloat16 *xqh,*xql,*xkh,*xkl,*xvh,*xvl;
    __nv_bfloat16 *wqh,*wql,*wkh,*wkl,*wvh,*wvl,*woh,*wol;
    __nv_bfloat16 *qh,*ql_,*kh,*kl,*vh,*vl,*ch,*cl;
    cudaGetSymbolAddress((void**)&xqh, g_xqh); cudaGetSymbolAddress((void**)&xql, g_xql);
    cudaGetSymbolAddress((void**)&xkh, g_xkh); cudaGetSymbolAddress((void**)&xkl, g_xkl);
    cudaGetSymbolAddress((void**)&xvh, g_xvh); cudaGetSymbolAddress((void**)&xvl, g_xvl);
    cudaGetSymbolAddress((void**)&wqh, g_wqh); cudaGetSymbolAddress((void**)&wql, g_wql);
    cudaGetSymbolAddress((void**)&wkh, g_wkh); cudaGetSymbolAddress((void**)&wkl, g_wkl);
    cudaGetSymbolAddress((void**)&wvh, g_wvh); cudaGetSymbolAddress((void**)&wvl, g_wvl);
    cudaGetSymbolAddress((void**)&woh, g_woh); cudaGetSymbolAddress((void**)&wol, g_wol);
    cudaGetSymbolAddress((void**)&qh, g_qh);   cudaGetSymbolAddress((void**)&ql_, g_ql);
    cudaGetSymbolAddress((void**)&kh, g_kh);   cudaGetSymbolAddress((void**)&kl, g_kl);
    cudaGetSymbolAddress((void**)&vh, g_vh);   cudaGetSymbolAddress((void**)&vl, g_vl);
    cudaGetSymbolAddress((void**)&ch, g_ch);   cudaGetSymbolAddress((void**)&cl, g_cl);

    cudaFuncSetAttribute(gemm_bf<true>,
                         cudaFuncAttributeMaxDynamicSharedMemorySize, GSMEM3);
    cudaFuncSetAttribute(gemm_bf<false>,
                         cudaFuncAttributeMaxDynamicSharedMemorySize, GSMEM3);
    cudaFuncSetAttribute(attn_mma_kernel,
                         cudaFuncAttributeMaxDynamicSharedMemorySize, ASMEM);

    const int nA4 = (int)(NA_/4), nW4 = (int)(NW_/4);

    Prep4 pi; pi.n4 = nA4;
    pi.x[0]=query; pi.h[0]=xqh; pi.l[0]=xql;
    pi.x[1]=key;   pi.h[1]=xkh; pi.l[1]=xkl;
    pi.x[2]=value; pi.h[2]=xvh; pi.l[2]=xvl;
    pi.x[3]=query; pi.h[3]=xqh; pi.l[3]=xql;   // unused
    prep_batch<<<dim3((nA4+255)/256, 3), 256>>>(pi);

    Prep4 pw; pw.n4 = nW4;
    pw.x[0]=Wq; pw.h[0]=wqh; pw.l[0]=wql;
    pw.x[1]=Wk; pw.h[1]=wkh; pw.l[1]=wkl;
    pw.x[2]=Wv; pw.h[2]=wvh; pw.l[2]=wvl;
    pw.x[3]=Wo; pw.h[3]=woh; pw.l[3]=wol;
    prep_batch<<<dim3((nW4+255)/256, 4), 256>>>(pw);

    GemmArgs3 gq;
    gq.g[0] = { xqh, xql, wqh, wql, bq, 0.125f, nullptr, qh,  ql_ };
    gq.g[1] = { xkh, xkl, wkh, wkl, bk, 1.0f,   nullptr, kh,  kl  };
    gq.g[2] = { xvh, xvl, wvh, wvl, bv, 1.0f,   nullptr, vh,  vl  };
    gemm_bf<true><<<dim3(M_/128, DM_/128, 3), 256, GSMEM3>>>(gq);

    attn_mma_kernel<<<dim3(S_/64, B_*H_), 256, ASMEM>>>();

    GemmArgs3 go;
    go.g[0] = { ch, cl, woh, wol, bo, 1.0f, out, nullptr, nullptr };
    go.g[1] = go.g[0];
    go.g[2] = go.g[0];
    gemm_bf<false><<<dim3(M_/128, DM_/128, 1), 256, GSMEM3>>>(go);
}

// round 11
// speedup vs baseline: 1.0785x; 1.0219x over previous
#include <cuda_runtime.h>
#include <cuda_bf16.h>
#include <cuda_fp16.h>
#include <cstdint>

#define B_   4
#define S_   2048
#define H_   16
#define DK_  64
#define DM_  1024
#define M_   (B_*S_)          // 8192
#define NA_  ((size_t)M_*DM_) // 8M elems
#define NW_  ((size_t)DM_*DM_)// 1M elems

// ---------------- scratch (__device__ globals; no allocs) ------------------
__device__ __nv_bfloat16 g_xqh[NA_], g_xql[NA_];
__device__ __nv_bfloat16 g_xkh[NA_], g_xkl[NA_];
__device__ __nv_bfloat16 g_xvh[NA_], g_xvl[NA_];
__device__ __nv_bfloat16 g_wqh[NW_], g_wql[NW_];
__device__ __nv_bfloat16 g_wkh[NW_], g_wkl[NW_];
__device__ __nv_bfloat16 g_wvh[NW_], g_wvl[NW_];
__device__ __nv_bfloat16 g_woh[NW_], g_wol[NW_];
__device__ __nv_bfloat16 g_qh[NA_], g_ql[NA_];
__device__ __nv_bfloat16 g_kh[NA_], g_kl[NA_];
__device__ __nv_bfloat16 g_vh[NA_], g_vl[NA_];
__device__ __nv_bfloat16 g_ch[NA_], g_cl[NA_];

// ---------------- PTX helpers ----------------------------------------------
__device__ __forceinline__ uint32_t smem_u32(const void* p) {
    uint32_t a;
    asm("{ .reg .u64 t; cvta.to.shared.u64 t, %1; cvt.u32.u64 %0, t; }"
        : "=r"(a) : "l"(p));
    return a;
}
__device__ __forceinline__ void ldsm_x4(uint32_t& r0, uint32_t& r1,
                                        uint32_t& r2, uint32_t& r3, uint32_t a) {
    asm volatile("ldmatrix.sync.aligned.m8n8.x4.shared.b16 {%0,%1,%2,%3}, [%4];"
                 : "=r"(r0), "=r"(r1), "=r"(r2), "=r"(r3) : "r"(a));
}
__device__ __forceinline__ void ldsm_x4t(uint32_t& r0, uint32_t& r1,
                                         uint32_t& r2, uint32_t& r3, uint32_t a) {
    asm volatile("ldmatrix.sync.aligned.m8n8.x4.trans.shared.b16 {%0,%1,%2,%3}, [%4];"
                 : "=r"(r0), "=r"(r1), "=r"(r2), "=r"(r3) : "r"(a));
}
__device__ __forceinline__ void mma_bf16(float* c,
                                         const uint32_t* a,
                                         uint32_t b0, uint32_t b1) {
    asm volatile("mma.sync.aligned.m16n8k16.row.col.f32.bf16.bf16.f32 "
                 "{%0,%1,%2,%3}, {%4,%5,%6,%7}, {%8,%9}, {%0,%1,%2,%3};"
                 : "+f"(c[0]), "+f"(c[1]), "+f"(c[2]), "+f"(c[3])
                 : "r"(a[0]), "r"(a[1]), "r"(a[2]), "r"(a[3]), "r"(b0), "r"(b1));
}
#define CP16(dst, src) \
    asm volatile("cp.async.cg.shared.global [%0], [%1], 16;" \
                 :: "r"(dst), "l"(src) : "memory")
#define CP_COMMIT() asm volatile("cp.async.commit_group;" ::: "memory")
#define CP_WAIT1()  asm volatile("cp.async.wait_group 1;"  ::: "memory")

__device__ __forceinline__ uint32_t pack_bf16(float x, float y) {
    __nv_bfloat162 t = __floats2bfloat162_rn(x, y);
    return reinterpret_cast<uint32_t&>(t);
}
__device__ __forceinline__ void split2(float x, float y, uint32_t& hi, uint32_t& lo) {
    __nv_bfloat16 hx = __float2bfloat16(x);
    __nv_bfloat16 hy = __float2bfloat16(y);
    __nv_bfloat162 h; h.x = hx; h.y = hy;
    hi = reinterpret_cast<uint32_t&>(h);
    lo = pack_bf16(x - __bfloat162float(hx), y - __bfloat162float(hy));
}

// exp2 of two values in one MUFU issue (ex2.approx.f16x2)
__device__ __forceinline__ float2 exp2pair(float a, float b) {
    uint32_t p, r;
    asm("cvt.rn.f16x2.f32 %0, %1, %2;" : "=r"(p) : "f"(b), "f"(a)); // lo=a, hi=b
    asm("ex2.approx.f16x2 %0, %1;" : "=r"(r) : "r"(p));
    const __half2 h = *reinterpret_cast<__half2*>(&r);
    return __half22float2(h);
}

// ---------------- prep: fp32 -> bf16 hi/lo planes (batched up to 4) ---------
struct Prep4 { const float* x[4]; __nv_bfloat16* h[4]; __nv_bfloat16* l[4]; int n4; };

__global__ __launch_bounds__(256)
void prep_batch(Prep4 pa)
{
    const int z = blockIdx.y;
    const int i = blockIdx.x * 256 + threadIdx.x;
    if (i >= pa.n4) return;
    const float4 v = __ldg((const float4*)pa.x[z] + i);
    uint32_t h0, l0, h1, l1;
    split2(v.x, v.y, h0, l0);
    split2(v.z, v.w, h1, l1);
    ((uint2*)pa.h[z])[i] = make_uint2(h0, h1);
    ((uint2*)pa.l[z])[i] = make_uint2(l0, l1);
}

// ===========================================================================
// GEMM: C[M,N] = A[M,K]*W[N,K]^T + bias   (bf16 hi/lo, 3-term mma)
// CTA 128x128, K-tile 32, 3-stage cp.async ring with wait_group 1.
// 64B rows with XOR swizzle: 96 KB smem, 2 CTAs/SM.
// ===========================================================================
#define GP3    (128*64)        // plane bytes 8192
#define GSTG3  (4*GP3)         // 32768
#define GSMEM3 (3*GSTG3)       // 98304
#define GKT2   (DM_/32)        // 32

struct GemmArgs {
    const __nv_bfloat16 *Ah, *Al, *Wh, *Wl;
    const float* bias;
    float scale;
    float* Cf;
    __nv_bfloat16 *Ch, *Cl;
};
struct GemmArgs3 { GemmArgs g[3]; };

template<bool SPLITO>
__global__ __launch_bounds__(256, 2)
void gemm_bf(GemmArgs3 aa)
{
    const GemmArgs ga = aa.g[blockIdx.z];
    extern __shared__ char smem[];
    const uint32_t sb = smem_u32(smem);
    const int tid = threadIdx.x;
    const int w = tid >> 5, l = tid & 31;
    const int wm = w & 3, wn = w >> 2;
    const int m0 = blockIdx.x * 128;
    const int n0 = blockIdx.y * 128;

    const int srow = tid >> 2;
    const int sch  = tid & 3;
    const uint32_t s_swz = (uint32_t)((srow >> 1) & 3);
    const uint32_t s_off = (uint32_t)(((uint32_t)(sch) ^ s_swz) << 4);

    auto stage = [&](int kt, int s3) {
        const uint32_t buf = sb + (uint32_t)s3 * GSTG3;
        const int k0 = kt * 32;
        #pragma unroll
        for (int i = 0; i < 2; i++) {
            const int row = srow + i*64;
            const uint32_t off = (uint32_t)(row*64) + s_off;
            CP16(buf + 0*GP3 + off, ga.Ah + (size_t)(m0+row)*DM_ + k0 + sch*8);
            CP16(buf + 1*GP3 + off, ga.Al + (size_t)(m0+row)*DM_ + k0 + sch*8);
            CP16(buf + 2*GP3 + off, ga.Wh + (size_t)(n0+row)*DM_ + k0 + sch*8);
            CP16(buf + 3*GP3 + off, ga.Wl + (size_t)(n0+row)*DM_ + k0 + sch*8);
        }
    };

    float acc[2][8][4];
    #pragma unroll
    for (int mt = 0; mt < 2; mt++)
        #pragma unroll
        for (int nt = 0; nt < 8; nt++)
            #pragma unroll
            for (int r = 0; r < 4; r++) acc[mt][nt][r] = 0.f;

    stage(0, 0); CP_COMMIT();
    stage(1, 1); CP_COMMIT();

    const uint32_t a_row = (uint32_t)(wm*32 + (l & 15));
    const uint32_t a_ch0 = (uint32_t)(l >> 4);
    const uint32_t a_swz = (a_row >> 1) & 3;
    const uint32_t b4row = (uint32_t)(wn*64 + ((l >> 4) & 1)*8 + (l & 7));
    const uint32_t b_ch0 = (uint32_t)((l >> 3) & 1);
    const uint32_t b_swz = (b4row >> 1) & 3;

    for (int kt = 0; kt < GKT2; kt++) {
        CP_WAIT1();
        __syncthreads();
        if (kt + 2 < GKT2) stage(kt+2, (kt+2)%3);
        CP_COMMIT();

        const uint32_t buf = sb + (uint32_t)((kt % 3) * GSTG3);
        #pragma unroll
        for (int ks = 0; ks < 2; ks++) {
            const uint32_t aoff = (((a_ch0 + ks*2) ^ a_swz) << 4);
            const uint32_t boff = (((b_ch0 + ks*2) ^ b_swz) << 4);
            uint32_t ah[2][4], al[2][4];
            #pragma unroll
            for (int mt = 0; mt < 2; mt++) {
                const uint32_t ao = (a_row + mt*16)*64 + aoff;
                ldsm_x4(ah[mt][0], ah[mt][1], ah[mt][2], ah[mt][3], buf + 0*GP3 + ao);
                ldsm_x4(al[mt][0], al[mt][1], al[mt][2], al[mt][3], buf + 1*GP3 + ao);
            }
            #pragma unroll
            for (int np = 0; np < 4; np++) {
                const uint32_t bo = (b4row + np*16)*64 + boff;
                uint32_t h0,h1,h2,h3, l0,l1,l2,l3;
                ldsm_x4(h0, h1, h2, h3, buf + 2*GP3 + bo);
                ldsm_x4(l0, l1, l2, l3, buf + 3*GP3 + bo);
                mma_bf16(acc[0][2*np  ], ah[0], h0, h1);
                mma_bf16(acc[1][2*np  ], ah[1], h0, h1);
                mma_bf16(acc[0][2*np+1], ah[0], h2, h3);
                mma_bf16(acc[1][2*np+1], ah[1], h2, h3);
                mma_bf16(acc[0][2*np  ], ah[0], l0, l1);
                mma_bf16(acc[1][2*np  ], ah[1], l0, l1);
                mma_bf16(acc[0][2*np+1], ah[0], l2, l3);
                mma_bf16(acc[1][2*np+1], ah[1], l2, l3);
                mma_bf16(acc[0][2*np  ], al[0], h0, h1);
                mma_bf16(acc[1][2*np  ], al[1], h0, h1);
                mma_bf16(acc[0][2*np+1], al[0], h2, h3);
                mma_bf16(acc[1][2*np+1], al[1], h2, h3);
            }
        }
    }

    // Epilogue
    #pragma unroll
    for (int mt = 0; mt < 2; mt++) {
        const int mrow = m0 + wm*32 + mt*16 + (l >> 2);
        #pragma unroll
        for (int nt = 0; nt < 8; nt++) {
            const int ncol = n0 + wn*64 + nt*8 + (l & 3)*2;
            const float2 bb = *(const float2*)(ga.bias + ncol);
            float2 o0 = { (acc[mt][nt][0] + bb.x)*ga.scale, (acc[mt][nt][1] + bb.y)*ga.scale };
            float2 o1 = { (acc[mt][nt][2] + bb.x)*ga.scale, (acc[mt][nt][3] + bb.y)*ga.scale };
            if (SPLITO) {
                const int h = ncol >> 6, d = ncol & 63;
                uint32_t hi, lo;
                const int b0i = mrow >> 11, s0i = mrow & (S_-1);
                size_t idx = ((size_t)((b0i*H_ + h)*S_ + s0i))*DK_ + d;
                split2(o0.x, o0.y, hi, lo);
                *(uint32_t*)(ga.Ch + idx) = hi;  *(uint32_t*)(ga.Cl + idx) = lo;
                const int m2 = mrow + 8;
                const int b1i = m2 >> 11, s1i = m2 & (S_-1);
                idx = ((size_t)((b1i*H_ + h)*S_ + s1i))*DK_ + d;
                split2(o1.x, o1.y, hi, lo);
                *(uint32_t*)(ga.Ch + idx) = hi;  *(uint32_t*)(ga.Cl + idx) = lo;
            } else {
                *(float2*)(ga.Cf + (size_t)mrow*DM_ + ncol) = o0;
                *(float2*)(ga.Cf + (size_t)(mrow+8)*DM_ + ncol) = o1;
            }
        }
    }
}

// ===========================================================================
// Flash attention: 64-query CTA, 8 warps (4m x 2n); wn splits the 64 keys.
// Scores in LOG2 domain (log2e folded into Q projection scale); exp via
// ex2.approx.f16x2 (1 MUFU per 2 scores). Independent per-half online
// softmax; single exact merge. 3-stage cp.async ring. 2 CTAs/SM.
// ===========================================================================
#define AP_   (64*144)        // plane bytes 9216
#define ASTG  (4*AP_)         // 36864
#define ASMEM (3*ASTG)        // 110592
#define ANB   (S_/64)         // 32 key blocks

__global__ __launch_bounds__(256, 2)
void attn_mma_kernel()
{
    extern __shared__ char smem[];
    const uint32_t sb = smem_u32(smem);
    const int tid = threadIdx.x;
    const int w = tid >> 5, l = tid & 31;
    const int wm = w & 3, wn = w >> 2;
    const int q0 = blockIdx.x * 64;
    const int bh = blockIdx.y;

    const __nv_bfloat16* qph = g_qh + (size_t)bh*S_*DK_;
    const __nv_bfloat16* qpl = g_ql + (size_t)bh*S_*DK_;
    const __nv_bfloat16* kph = g_kh + (size_t)bh*S_*DK_;
    const __nv_bfloat16* kpl = g_kl + (size_t)bh*S_*DK_;
    const __nv_bfloat16* vph = g_vh + (size_t)bh*S_*DK_;
    const __nv_bfloat16* vpl = g_vl + (size_t)bh*S_*DK_;

    const int srow = tid >> 3;
    const int sch  = tid & 7;

    auto stage = [&](int j, int s3) {
        const uint32_t buf = sb + (uint32_t)s3 * ASTG;
        const int r0 = j*64;
        #pragma unroll
        for (int i = 0; i < 2; i++) {
            const int row = srow + i*32;
            const uint32_t off = (uint32_t)(row*144 + sch*16);
            const size_t g = (size_t)(r0+row)*DK_ + sch*8;
            CP16(buf + 0*AP_ + off, kph + g);
            CP16(buf + 1*AP_ + off, kpl + g);
            CP16(buf + 2*AP_ + off, vph + g);
            CP16(buf + 3*AP_ + off, vpl + g);
        }
    };

    stage(0, 0); CP_COMMIT();
    stage(1, 1); CP_COMMIT();

    // Q fragments (pre-scaled by 0.125*log2e in projection)
    uint32_t qh[4][4], ql[4][4];
    {
        const int r1 = q0 + wm*16 + (l >> 2);
        #pragma unroll
        for (int ks = 0; ks < 4; ks++) {
            #pragma unroll
            for (int rg = 0; rg < 4; rg++) {
                const int row = r1 + ((rg & 1) ? 8 : 0);
                const int col = ks*16 + (l & 3)*2 + ((rg & 2) ? 8 : 0);
                qh[ks][rg] = *(const uint32_t*)(qph + (size_t)row*DK_ + col);
                ql[ks][rg] = *(const uint32_t*)(qpl + (size_t)row*DK_ + col);
            }
        }
    }

    float o[8][4];
    #pragma unroll
    for (int t = 0; t < 8; t++)
        #pragma unroll
        for (int r = 0; r < 4; r++) o[t][r] = 0.f;
    float m1 = -1e30f, m2 = -1e30f, l1 = 0.f, l2 = 0.f;

    const uint32_t kqrow = (uint32_t)(wn*32 + ((l >> 4) & 1)*8 + (l & 7));
    const uint32_t kb_kof = (uint32_t)(8 * ((l >> 3) & 1));
    const uint32_t vrow_b = (uint32_t)(((l >> 3) & 1)*8 + (l & 7));
    const uint32_t vcol_b = (uint32_t)(((l >> 4) & 1)*8);

    for (int j = 0; j < ANB; j++) {
        CP_WAIT1();
        __syncthreads();
        if (j + 2 < ANB) stage(j+2, (j+2)%3);
        CP_COMMIT();

        const uint32_t buf = sb + (uint32_t)((j % 3) * ASTG);

        // S = Q K^T (log2 domain) over this warp's 32 keys
        float s[4][4];
        #pragma unroll
        for (int t = 0; t < 4; t++)
            #pragma unroll
            for (int r = 0; r < 4; r++) s[t][r] = 0.f;

        #pragma unroll
        for (int ks = 0; ks < 4; ks++) {
            uint32_t kh2[2][4], kl2[2][4];
            #pragma unroll
            for (int tp = 0; tp < 2; tp++) {
                const uint32_t bo = (kqrow + tp*16)*144 + (ks*16 + kb_kof)*2;
                ldsm_x4(kh2[tp][0], kh2[tp][1], kh2[tp][2], kh2[tp][3], buf + 0*AP_ + bo);
                ldsm_x4(kl2[tp][0], kl2[tp][1], kl2[tp][2], kl2[tp][3], buf + 1*AP_ + bo);
            }
            mma_bf16(s[0], qh[ks], kh2[0][0], kh2[0][1]);
            mma_bf16(s[1], qh[ks], kh2[0][2], kh2[0][3]);
            mma_bf16(s[2], qh[ks], kh2[1][0], kh2[1][1]);
            mma_bf16(s[3], qh[ks], kh2[1][2], kh2[1][3]);
            mma_bf16(s[0], qh[ks], kl2[0][0], kl2[0][1]);
            mma_bf16(s[1], qh[ks], kl2[0][2], kl2[0][3]);
            mma_bf16(s[2], qh[ks], kl2[1][0], kl2[1][1]);
            mma_bf16(s[3], qh[ks], kl2[1][2], kl2[1][3]);
            mma_bf16(s[0], ql[ks], kh2[0][0], kh2[0][1]);
            mma_bf16(s[1], ql[ks], kh2[0][2], kh2[0][3]);
            mma_bf16(s[2], ql[ks], kh2[1][0], kh2[1][1]);
            mma_bf16(s[3], ql[ks], kh2[1][2], kh2[1][3]);
        }

        // independent online softmax (log2 domain)
        float rm1 = -1e30f, rm2 = -1e30f;
        #pragma unroll
        for (int t = 0; t < 4; t++) {
            rm1 = fmaxf(rm1, fmaxf(s[t][0], s[t][1]));
            rm2 = fmaxf(rm2, fmaxf(s[t][2], s[t][3]));
        }
        rm1 = fmaxf(rm1, __shfl_xor_sync(0xffffffffu, rm1, 1));
        rm1 = fmaxf(rm1, __shfl_xor_sync(0xffffffffu, rm1, 2));
        rm2 = fmaxf(rm2, __shfl_xor_sync(0xffffffffu, rm2, 1));
        rm2 = fmaxf(rm2, __shfl_xor_sync(0xffffffffu, rm2, 2));

        const float mn1 = fmaxf(m1, rm1), mn2 = fmaxf(m2, rm2);
        const float al1 = exp2f(m1 - mn1), al2 = exp2f(m2 - mn2);
        float sum1 = 0.f, sum2 = 0.f;
        #pragma unroll
        for (int t = 0; t < 4; t++) {
            const float2 e01 = exp2pair(s[t][0] - mn1, s[t][1] - mn1);
            const float2 e23 = exp2pair(s[t][2] - mn2, s[t][3] - mn2);
            s[t][0] = e01.x; s[t][1] = e01.y;
            s[t][2] = e23.x; s[t][3] = e23.y;
            sum1 += e01.x + e01.y;
            sum2 += e23.x + e23.y;
        }
        sum1 += __shfl_xor_sync(0xffffffffu, sum1, 1);
        sum1 += __shfl_xor_sync(0xffffffffu, sum1, 2);
        sum2 += __shfl_xor_sync(0xffffffffu, sum2, 1);
        sum2 += __shfl_xor_sync(0xffffffffu, sum2, 2);
        l1 = l1*al1 + sum1; l2 = l2*al2 + sum2;
        m1 = mn1; m2 = mn2;
        #pragma unroll
        for (int t = 0; t < 8; t++) {
            o[t][0] *= al1; o[t][1] *= al1;
            o[t][2] *= al2; o[t][3] *= al2;
        }

        // O += P @ V over this warp's keys (2 k16 steps)
        #pragma unroll
        for (int kss = 0; kss < 2; kss++) {
            const int ks_g = wn*2 + kss;
            uint32_t ph[4], pl[4];
            split2(s[2*kss  ][0], s[2*kss  ][1], ph[0], pl[0]);
            split2(s[2*kss  ][2], s[2*kss  ][3], ph[1], pl[1]);
            split2(s[2*kss+1][0], s[2*kss+1][1], ph[2], pl[2]);
            split2(s[2*kss+1][2], s[2*kss+1][3], ph[3], pl[3]);
            const uint32_t vrow = (uint32_t)(ks_g*16) + vrow_b;
            #pragma unroll
            for (int np = 0; np < 4; np++) {
                const uint32_t vo = vrow*144 + (np*16 + vcol_b)*2;
                uint32_t h0,h1,h2,h3, l0,l1_,l2,l3;
                ldsm_x4t(h0, h1, h2, h3, buf + 2*AP_ + vo);
                ldsm_x4t(l0, l1_, l2, l3, buf + 3*AP_ + vo);
                mma_bf16(o[2*np  ], ph, h0, h1);
                mma_bf16(o[2*np+1], ph, h2, h3);
                mma_bf16(o[2*np  ], ph, l0, l1_);
                mma_bf16(o[2*np+1], ph, l2, l3);
                mma_bf16(o[2*np  ], pl, h0, h1);
                mma_bf16(o[2*np+1], pl, h2, h3);
            }
        }
    }

    // -------- final merge of the two independent key-half streams ----------
    __syncthreads();
    float* comb = (float*)smem;          // O: 64 rows x 66 floats
    float* cm   = comb + 64*66;          // m per row
    float* clv  = cm + 64;               // l per row
    const int rl  = wm*16 + (l >> 2);
    const int cl2 = (l & 3)*2;
    if (wn == 1) {
        if ((l & 3) == 0) {
            cm[rl]     = m1;  cm[rl+8]  = m2;
            clv[rl]    = l1;  clv[rl+8] = l2;
        }
        #pragma unroll
        for (int t = 0; t < 8; t++) {
            *(float2*)&comb[ rl     *66 + t*8 + cl2] = make_float2(o[t][0], o[t][1]);
            *(float2*)&comb[(rl + 8)*66 + t*8 + cl2] = make_float2(o[t][2], o[t][3]);
        }
    }
    __syncthreads();
    if (wn == 0) {
        const float mB1 = cm[rl], mB2 = cm[rl+8];
        const float lB1 = clv[rl], lB2 = clv[rl+8];
        const float mw1 = fmaxf(m1, mB1), mw2 = fmaxf(m2, mB2);
        const float fs1 = exp2f(m1 - mw1), fb1 = exp2f(mB1 - mw1);
        const float fs2 = exp2f(m2 - mw2), fb2 = exp2f(mB2 - mw2);
        const float i1 = 1.f / (l1*fs1 + lB1*fb1);
        const float i2 = 1.f / (l2*fs2 + lB2*fb2);
        const int b = bh >> 4, h = bh & 15;
        const int row1 = q0 + rl;
        #pragma unroll
        for (int t = 0; t < 8; t++) {
            const float2 p0 = *(const float2*)&comb[ rl     *66 + t*8 + cl2];
            const float2 p1 = *(const float2*)&comb[(rl + 8)*66 + t*8 + cl2];
            const int col = h*DK_ + t*8 + cl2;
            uint32_t hi, lo;
            size_t idx = (size_t)(b*S_ + row1)*DM_ + col;
            split2((o[t][0]*fs1 + p0.x*fb1)*i1, (o[t][1]*fs1 + p0.y*fb1)*i1, hi, lo);
            *(uint32_t*)(g_ch + idx) = hi;  *(uint32_t*)(g_cl + idx) = lo;
            idx = (size_t)(b*S_ + row1 + 8)*DM_ + col;
            split2((o[t][2]*fs2 + p1.x*fb2)*i2, (o[t][3]*fs2 + p1.y*fb2)*i2, hi, lo);
            *(uint32_t*)(g_ch + idx) = hi;  *(uint32_t*)(g_cl + idx) = lo;
        }
    }
}

// ===========================================================================
extern "C" void kernel_launch(void* const* d_in, const int* in_sizes, int n_in,
                              void* d_out, int out_size)
{
    (void)in_sizes; (void)n_in; (void)out_size;
    const float* query = (const float*)d_in[0];
    const float* key   = (const float*)d_in[1];
    const float* value = (const float*)d_in[2];
    const float* Wq    = (const float*)d_in[3];
    const float* bq    = (const float*)d_in[4];
    const float* Wk    = (const float*)d_in[5];
    const float* bk    = (const float*)d_in[6];
    const float* Wv    = (const float*)d_in[7];
    const float* bv    = (const float*)d_in[8];
    const float* Wo    = (const float*)d_in[9];
    const float* bo    = (const float*)d_in[10];
    float* out = (float*)d_out;

    __nv_bfloat16 *xqh,*xql,*xkh,*xkl,*xvh,*xvl;
    __nv_bfloat16 *wqh,*wql,*wkh,*wkl,*wvh,*wvl,*woh,*wol;
    __nv_bfloat16 *qh,*ql_,*kh,*kl,*vh,*vl,*ch,*cl;
    cudaGetSymbolAddress((void**)&xqh, g_xqh); cudaGetSymbolAddress((void**)&xql, g_xql);
    cudaGetSymbolAddress((void**)&xkh, g_xkh); cudaGetSymbolAddress((void**)&xkl, g_xkl);
    cudaGetSymbolAddress((void**)&xvh, g_xvh); cudaGetSymbolAddress((void**)&xvl, g_xvl);
    cudaGetSymbolAddress((void**)&wqh, g_wqh); cudaGetSymbolAddress((void**)&wql, g_wql);
    cudaGetSymbolAddress((void**)&wkh, g_wkh); cudaGetSymbolAddress((void**)&wkl, g_wkl);
    cudaGetSymbolAddress((void**)&wvh, g_wvh); cudaGetSymbolAddress((void**)&wvl, g_wvl);
    cudaGetSymbolAddress((void**)&woh, g_woh); cudaGetSymbolAddress((void**)&wol, g_wol);
    cudaGetSymbolAddress((void**)&qh, g_qh);   cudaGetSymbolAddress((void**)&ql_, g_ql);
    cudaGetSymbolAddress((void**)&kh, g_kh);   cudaGetSymbolAddress((void**)&kl, g_kl);
    cudaGetSymbolAddress((void**)&vh, g_vh);   cudaGetSymbolAddress((void**)&vl, g_vl);
    cudaGetSymbolAddress((void**)&ch, g_ch);   cudaGetSymbolAddress((void**)&cl, g_cl);

    cudaFuncSetAttribute(gemm_bf<true>,
                         cudaFuncAttributeMaxDynamicSharedMemorySize, GSMEM3);
    cudaFuncSetAttribute(gemm_bf<false>,
                         cudaFuncAttributeMaxDynamicSharedMemorySize, GSMEM3);
    cudaFuncSetAttribute(attn_mma_kernel,
                         cudaFuncAttributeMaxDynamicSharedMemorySize, ASMEM);

    const int nA4 = (int)(NA_/4), nW4 = (int)(NW_/4);

    Prep4 pi; pi.n4 = nA4;
    pi.x[0]=query; pi.h[0]=xqh; pi.l[0]=xql;
    pi.x[1]=key;   pi.h[1]=xkh; pi.l[1]=xkl;
    pi.x[2]=value; pi.h[2]=xvh; pi.l[2]=xvl;
    pi.x[3]=query; pi.h[3]=xqh; pi.l[3]=xql;   // unused
    prep_batch<<<dim3((nA4+255)/256, 3), 256>>>(pi);

    Prep4 pw; pw.n4 = nW4;
    pw.x[0]=Wq; pw.h[0]=wqh; pw.l[0]=wql;
    pw.x[1]=Wk; pw.h[1]=wkh; pw.l[1]=wkl;
    pw.x[2]=Wv; pw.h[2]=wvh; pw.l[2]=wvl;
    pw.x[3]=Wo; pw.h[3]=woh; pw.l[3]=wol;
    prep_batch<<<dim3((nW4+255)/256, 4), 256>>>(pw);

    // Q scale folds 1/sqrt(d_k) AND log2(e): scores land in log2 domain
    const float QSCALE = 0.125f * 1.4426950408889634f;

    GemmArgs3 gq;
    gq.g[0] = { xqh, xql, wqh, wql, bq, QSCALE, nullptr, qh,  ql_ };
    gq.g[1] = { xkh, xkl, wkh, wkl, bk, 1.0f,   nullptr, kh,  kl  };
    gq.g[2] = { xvh, xvl, wvh, wvl, bv, 1.0f,   nullptr, vh,  vl  };
    gemm_bf<true><<<dim3(M_/128, DM_/128, 3), 256, GSMEM3>>>(gq);

    attn_mma_kernel<<<dim3(S_/64, B_*H_), 256, ASMEM>>>();

    GemmArgs3 go;
    go.g[0] = { ch, cl, woh, wol, bo, 1.0f, out, nullptr, nullptr };
    go.g[1] = go.g[0];
    go.g[2] = go.g[0];
    gemm_bf<false><<<dim3(M_/128, DM_/128, 1), 256, GSMEM3>>>(go);
}

// round 12
// speedup vs baseline: 1.1005x; 1.0203x over previous
#include <cuda_runtime.h>
#include <cuda_bf16.h>
#include <cuda_fp16.h>
#include <cstdint>

#define B_   4
#define S_   2048
#define H_   16
#define DK_  64
#define DM_  1024
#define M_   (B_*S_)          // 8192
#define NA_  ((size_t)M_*DM_) // 8M elems
#define NW_  ((size_t)DM_*DM_)// 1M elems

// ---------------- scratch (__device__ globals; no allocs) ------------------
__device__ __nv_bfloat16 g_xqh[NA_], g_xql[NA_];
__device__ __nv_bfloat16 g_xkh[NA_], g_xkl[NA_];
__device__ __nv_bfloat16 g_xvh[NA_], g_xvl[NA_];
__device__ __nv_bfloat16 g_wqh[NW_], g_wql[NW_];
__device__ __nv_bfloat16 g_wkh[NW_], g_wkl[NW_];
__device__ __nv_bfloat16 g_wvh[NW_], g_wvl[NW_];
__device__ __nv_bfloat16 g_woh[NW_], g_wol[NW_];
__device__ __nv_bfloat16 g_qh[NA_], g_ql[NA_];
__device__ __nv_bfloat16 g_kh[NA_], g_kl[NA_];
__device__ __nv_bfloat16 g_vh[NA_], g_vl[NA_];
__device__ __nv_bfloat16 g_ch[NA_], g_cl[NA_];

// ---------------- PTX helpers ----------------------------------------------
__device__ __forceinline__ uint32_t smem_u32(const void* p) {
    uint32_t a;
    asm("{ .reg .u64 t; cvta.to.shared.u64 t, %1; cvt.u32.u64 %0, t; }"
        : "=r"(a) : "l"(p));
    return a;
}
__device__ __forceinline__ void ldsm_x4(uint32_t& r0, uint32_t& r1,
                                        uint32_t& r2, uint32_t& r3, uint32_t a) {
    asm volatile("ldmatrix.sync.aligned.m8n8.x4.shared.b16 {%0,%1,%2,%3}, [%4];"
                 : "=r"(r0), "=r"(r1), "=r"(r2), "=r"(r3) : "r"(a));
}
__device__ __forceinline__ void ldsm_x4t(uint32_t& r0, uint32_t& r1,
                                         uint32_t& r2, uint32_t& r3, uint32_t a) {
    asm volatile("ldmatrix.sync.aligned.m8n8.x4.trans.shared.b16 {%0,%1,%2,%3}, [%4];"
                 : "=r"(r0), "=r"(r1), "=r"(r2), "=r"(r3) : "r"(a));
}
__device__ __forceinline__ void mma_bf16(float* c,
                                         const uint32_t* a,
                                         uint32_t b0, uint32_t b1) {
    asm volatile("mma.sync.aligned.m16n8k16.row.col.f32.bf16.bf16.f32 "
                 "{%0,%1,%2,%3}, {%4,%5,%6,%7}, {%8,%9}, {%0,%1,%2,%3};"
                 : "+f"(c[0]), "+f"(c[1]), "+f"(c[2]), "+f"(c[3])
                 : "r"(a[0]), "r"(a[1]), "r"(a[2]), "r"(a[3]), "r"(b0), "r"(b1));
}
#define CP16(dst, src) \
    asm volatile("cp.async.cg.shared.global [%0], [%1], 16;" \
                 :: "r"(dst), "l"(src) : "memory")
#define CP_COMMIT() asm volatile("cp.async.commit_group;" ::: "memory")
#define CP_WAIT1()  asm volatile("cp.async.wait_group 1;"  ::: "memory")

__device__ __forceinline__ uint32_t pack_bf16(float x, float y) {
    __nv_bfloat162 t = __floats2bfloat162_rn(x, y);
    return reinterpret_cast<uint32_t&>(t);
}
__device__ __forceinline__ void split2(float x, float y, uint32_t& hi, uint32_t& lo) {
    __nv_bfloat16 hx = __float2bfloat16(x);
    __nv_bfloat16 hy = __float2bfloat16(y);
    __nv_bfloat162 h; h.x = hx; h.y = hy;
    hi = reinterpret_cast<uint32_t&>(h);
    lo = pack_bf16(x - __bfloat162float(hx), y - __bfloat162float(hy));
}

// exp2 of two values in one MUFU issue (ex2.approx.f16x2)
__device__ __forceinline__ float2 exp2pair(float a, float b) {
    uint32_t p, r;
    asm("cvt.rn.f16x2.f32 %0, %1, %2;" : "=r"(p) : "f"(b), "f"(a)); // lo=a, hi=b
    asm("ex2.approx.f16x2 %0, %1;" : "=r"(r) : "r"(p));
    const __half2 h = *reinterpret_cast<__half2*>(&r);
    return __half22float2(h);
}

// ---------------- prep: fp32 -> bf16 hi/lo planes (batched up to 4) ---------
struct Prep4 { const float* x[4]; __nv_bfloat16* h[4]; __nv_bfloat16* l[4]; int n4; };

__global__ __launch_bounds__(256)
void prep_batch(Prep4 pa)
{
    const int z = blockIdx.y;
    const int i = blockIdx.x * 256 + threadIdx.x;
    if (i >= pa.n4) return;
    const float4 v = __ldg((const float4*)pa.x[z] + i);
    uint32_t h0, l0, h1, l1;
    split2(v.x, v.y, h0, l0);
    split2(v.z, v.w, h1, l1);
    ((uint2*)pa.h[z])[i] = make_uint2(h0, h1);
    ((uint2*)pa.l[z])[i] = make_uint2(l0, l1);
}

// ===========================================================================
// GEMM: C[M,N] = A[M,K]*W[N,K]^T + bias   (bf16 hi/lo, 3-term mma)
// CTA 128x128, K-tile 32, 3-stage cp.async ring with wait_group 1.
// 64B rows with XOR swizzle: 96 KB smem, 2 CTAs/SM.
// ===========================================================================
#define GP3    (128*64)        // plane bytes 8192
#define GSTG3  (4*GP3)         // 32768
#define GSMEM3 (3*GSTG3)       // 98304
#define GKT2   (DM_/32)        // 32

struct GemmArgs {
    const __nv_bfloat16 *Ah, *Al, *Wh, *Wl;
    const float* bias;
    float scale;
    float* Cf;
    __nv_bfloat16 *Ch, *Cl;
};
struct GemmArgs3 { GemmArgs g[3]; };

template<bool SPLITO>
__global__ __launch_bounds__(256, 2)
void gemm_bf(GemmArgs3 aa)
{
    const GemmArgs ga = aa.g[blockIdx.z];
    extern __shared__ char smem[];
    const uint32_t sb = smem_u32(smem);
    const int tid = threadIdx.x;
    const int w = tid >> 5, l = tid & 31;
    const int wm = w & 3, wn = w >> 2;
    const int m0 = blockIdx.x * 128;
    const int n0 = blockIdx.y * 128;

    const int srow = tid >> 2;
    const int sch  = tid & 3;
    const uint32_t s_swz = (uint32_t)((srow >> 1) & 3);
    const uint32_t s_off = (uint32_t)(((uint32_t)(sch) ^ s_swz) << 4);

    auto stage = [&](int kt, int s3) {
        const uint32_t buf = sb + (uint32_t)s3 * GSTG3;
        const int k0 = kt * 32;
        #pragma unroll
        for (int i = 0; i < 2; i++) {
            const int row = srow + i*64;
            const uint32_t off = (uint32_t)(row*64) + s_off;
            CP16(buf + 0*GP3 + off, ga.Ah + (size_t)(m0+row)*DM_ + k0 + sch*8);
            CP16(buf + 1*GP3 + off, ga.Al + (size_t)(m0+row)*DM_ + k0 + sch*8);
            CP16(buf + 2*GP3 + off, ga.Wh + (size_t)(n0+row)*DM_ + k0 + sch*8);
            CP16(buf + 3*GP3 + off, ga.Wl + (size_t)(n0+row)*DM_ + k0 + sch*8);
        }
    };

    float acc[2][8][4];
    #pragma unroll
    for (int mt = 0; mt < 2; mt++)
        #pragma unroll
        for (int nt = 0; nt < 8; nt++)
            #pragma unroll
            for (int r = 0; r < 4; r++) acc[mt][nt][r] = 0.f;

    stage(0, 0); CP_COMMIT();
    stage(1, 1); CP_COMMIT();

    const uint32_t a_row = (uint32_t)(wm*32 + (l & 15));
    const uint32_t a_ch0 = (uint32_t)(l >> 4);
    const uint32_t a_swz = (a_row >> 1) & 3;
    const uint32_t b4row = (uint32_t)(wn*64 + ((l >> 4) & 1)*8 + (l & 7));
    const uint32_t b_ch0 = (uint32_t)((l >> 3) & 1);
    const uint32_t b_swz = (b4row >> 1) & 3;

    for (int kt = 0; kt < GKT2; kt++) {
        CP_WAIT1();
        __syncthreads();
        if (kt + 2 < GKT2) stage(kt+2, (kt+2)%3);
        CP_COMMIT();

        const uint32_t buf = sb + (uint32_t)((kt % 3) * GSTG3);
        #pragma unroll
        for (int ks = 0; ks < 2; ks++) {
            const uint32_t aoff = (((a_ch0 + ks*2) ^ a_swz) << 4);
            const uint32_t boff = (((b_ch0 + ks*2) ^ b_swz) << 4);
            uint32_t ah[2][4], al[2][4];
            #pragma unroll
            for (int mt = 0; mt < 2; mt++) {
                const uint32_t ao = (a_row + mt*16)*64 + aoff;
                ldsm_x4(ah[mt][0], ah[mt][1], ah[mt][2], ah[mt][3], buf + 0*GP3 + ao);
                ldsm_x4(al[mt][0], al[mt][1], al[mt][2], al[mt][3], buf + 1*GP3 + ao);
            }
            #pragma unroll
            for (int np = 0; np < 4; np++) {
                const uint32_t bo = (b4row + np*16)*64 + boff;
                uint32_t h0,h1,h2,h3, l0,l1,l2,l3;
                ldsm_x4(h0, h1, h2, h3, buf + 2*GP3 + bo);
                ldsm_x4(l0, l1, l2, l3, buf + 3*GP3 + bo);
                mma_bf16(acc[0][2*np  ], ah[0], h0, h1);
                mma_bf16(acc[1][2*np  ], ah[1], h0, h1);
                mma_bf16(acc[0][2*np+1], ah[0], h2, h3);
                mma_bf16(acc[1][2*np+1], ah[1], h2, h3);
                mma_bf16(acc[0][2*np  ], ah[0], l0, l1);
                mma_bf16(acc[1][2*np  ], ah[1], l0, l1);
                mma_bf16(acc[0][2*np+1], ah[0], l2, l3);
                mma_bf16(acc[1][2*np+1], ah[1], l2, l3);
                mma_bf16(acc[0][2*np  ], al[0], h0, h1);
                mma_bf16(acc[1][2*np  ], al[1], h0, h1);
                mma_bf16(acc[0][2*np+1], al[0], h2, h3);
                mma_bf16(acc[1][2*np+1], al[1], h2, h3);
            }
        }
    }

    // Epilogue
    #pragma unroll
    for (int mt = 0; mt < 2; mt++) {
        const int mrow = m0 + wm*32 + mt*16 + (l >> 2);
        #pragma unroll
        for (int nt = 0; nt < 8; nt++) {
            const int ncol = n0 + wn*64 + nt*8 + (l & 3)*2;
            const float2 bb = *(const float2*)(ga.bias + ncol);
            float2 o0 = { (acc[mt][nt][0] + bb.x)*ga.scale, (acc[mt][nt][1] + bb.y)*ga.scale };
            float2 o1 = { (acc[mt][nt][2] + bb.x)*ga.scale, (acc[mt][nt][3] + bb.y)*ga.scale };
            if (SPLITO) {
                const int h = ncol >> 6, d = ncol & 63;
                uint32_t hi, lo;
                const int b0i = mrow >> 11, s0i = mrow & (S_-1);
                size_t idx = ((size_t)((b0i*H_ + h)*S_ + s0i))*DK_ + d;
                split2(o0.x, o0.y, hi, lo);
                *(uint32_t*)(ga.Ch + idx) = hi;  *(uint32_t*)(ga.Cl + idx) = lo;
                const int m2 = mrow + 8;
                const int b1i = m2 >> 11, s1i = m2 & (S_-1);
                idx = ((size_t)((b1i*H_ + h)*S_ + s1i))*DK_ + d;
                split2(o1.x, o1.y, hi, lo);
                *(uint32_t*)(ga.Ch + idx) = hi;  *(uint32_t*)(ga.Cl + idx) = lo;
            } else {
                *(float2*)(ga.Cf + (size_t)mrow*DM_ + ncol) = o0;
                *(float2*)(ga.Cf + (size_t)(mrow+8)*DM_ + ncol) = o1;
            }
        }
    }
}

// ===========================================================================
// Flash attention: 64-query CTA, 8 warps in TWO INDEPENDENT GROUPS (wn=0/1),
// each owning 32 of every 64 keys. Each group stages its own half-rows of
// the K/V planes and syncs on its own named barrier -> the groups drift and
// their softmax phases overlap the other group's MMAs. Scores in log2
// domain; exp via ex2.approx.f16x2. Single exact merge at the end.
// 3-stage cp.async ring. 2 CTAs/SM.
// ===========================================================================
#define AP_   (64*144)        // plane bytes 9216
#define ASTG  (4*AP_)         // 36864
#define ASMEM (3*ASTG)        // 110592
#define ANB   (S_/64)         // 32 key blocks

#define BAR_G(gid) \
    asm volatile("bar.sync %0, %1;" :: "r"((gid)+1), "r"(128) : "memory")

__global__ __launch_bounds__(256, 2)
void attn_mma_kernel()
{
    extern __shared__ char smem[];
    const uint32_t sb = smem_u32(smem);
    const int tid = threadIdx.x;
    const int w = tid >> 5, l = tid & 31;
    const int wm = w & 3, wn = w >> 2;        // wn = group id
    const int q0 = blockIdx.x * 64;
    const int bh = blockIdx.y;

    const __nv_bfloat16* qph = g_qh + (size_t)bh*S_*DK_;
    const __nv_bfloat16* qpl = g_ql + (size_t)bh*S_*DK_;
    const __nv_bfloat16* kph = g_kh + (size_t)bh*S_*DK_;
    const __nv_bfloat16* kpl = g_kl + (size_t)bh*S_*DK_;
    const __nv_bfloat16* vph = g_vh + (size_t)bh*S_*DK_;
    const __nv_bfloat16* vpl = g_vl + (size_t)bh*S_*DK_;

    // group-local staging: 32 rows (this group's key half) x 8 chunks
    const int gtid = tid & 127;
    const int srow = gtid >> 3;     // 0..15
    const int sch  = gtid & 7;

    auto stage = [&](int j, int s3) {
        const uint32_t buf = sb + (uint32_t)s3 * ASTG;
        const int r0 = j*64 + wn*32;
        #pragma unroll
        for (int i = 0; i < 2; i++) {
            const int row = srow + i*16;              // 0..31 within half
            const uint32_t off = (uint32_t)((wn*32 + row)*144 + sch*16);
            const size_t g = (size_t)(r0 + row)*DK_ + sch*8;
            CP16(buf + 0*AP_ + off, kph + g);
            CP16(buf + 1*AP_ + off, kpl + g);
            CP16(buf + 2*AP_ + off, vph + g);
            CP16(buf + 3*AP_ + off, vpl + g);
        }
    };

    stage(0, 0); CP_COMMIT();
    stage(1, 1); CP_COMMIT();

    // Q fragments (pre-scaled by 0.125*log2e in projection)
    uint32_t qh[4][4], ql[4][4];
    {
        const int r1 = q0 + wm*16 + (l >> 2);
        #pragma unroll
        for (int ks = 0; ks < 4; ks++) {
            #pragma unroll
            for (int rg = 0; rg < 4; rg++) {
                const int row = r1 + ((rg & 1) ? 8 : 0);
                const int col = ks*16 + (l & 3)*2 + ((rg & 2) ? 8 : 0);
                qh[ks][rg] = *(const uint32_t*)(qph + (size_t)row*DK_ + col);
                ql[ks][rg] = *(const uint32_t*)(qpl + (size_t)row*DK_ + col);
            }
        }
    }

    float o[8][4];
    #pragma unroll
    for (int t = 0; t < 8; t++)
        #pragma unroll
        for (int r = 0; r < 4; r++) o[t][r] = 0.f;
    float m1 = -1e30f, m2 = -1e30f, l1 = 0.f, l2 = 0.f;

    const uint32_t kqrow = (uint32_t)(wn*32 + ((l >> 4) & 1)*8 + (l & 7));
    const uint32_t kb_kof = (uint32_t)(8 * ((l >> 3) & 1));
    const uint32_t vrow_b = (uint32_t)(((l >> 3) & 1)*8 + (l & 7));
    const uint32_t vcol_b = (uint32_t)(((l >> 4) & 1)*8);

    for (int j = 0; j < ANB; j++) {
        CP_WAIT1();
        BAR_G(wn);
        if (j + 2 < ANB) stage(j+2, (j+2)%3);
        CP_COMMIT();

        const uint32_t buf = sb + (uint32_t)((j % 3) * ASTG);

        // S = Q K^T (log2 domain) over this group's 32 keys
        float s[4][4];
        #pragma unroll
        for (int t = 0; t < 4; t++)
            #pragma unroll
            for (int r = 0; r < 4; r++) s[t][r] = 0.f;

        #pragma unroll
        for (int ks = 0; ks < 4; ks++) {
            uint32_t kh2[2][4], kl2[2][4];
            #pragma unroll
            for (int tp = 0; tp < 2; tp++) {
                const uint32_t bo = (kqrow + tp*16)*144 + (ks*16 + kb_kof)*2;
                ldsm_x4(kh2[tp][0], kh2[tp][1], kh2[tp][2], kh2[tp][3], buf + 0*AP_ + bo);
                ldsm_x4(kl2[tp][0], kl2[tp][1], kl2[tp][2], kl2[tp][3], buf + 1*AP_ + bo);
            }
            mma_bf16(s[0], qh[ks], kh2[0][0], kh2[0][1]);
            mma_bf16(s[1], qh[ks], kh2[0][2], kh2[0][3]);
            mma_bf16(s[2], qh[ks], kh2[1][0], kh2[1][1]);
            mma_bf16(s[3], qh[ks], kh2[1][2], kh2[1][3]);
            mma_bf16(s[0], qh[ks], kl2[0][0], kl2[0][1]);
            mma_bf16(s[1], qh[ks], kl2[0][2], kl2[0][3]);
            mma_bf16(s[2], qh[ks], kl2[1][0], kl2[1][1]);
            mma_bf16(s[3], qh[ks], kl2[1][2], kl2[1][3]);
            mma_bf16(s[0], ql[ks], kh2[0][0], kh2[0][1]);
            mma_bf16(s[1], ql[ks], kh2[0][2], kh2[0][3]);
            mma_bf16(s[2], ql[ks], kh2[1][0], kh2[1][1]);
            mma_bf16(s[3], ql[ks], kh2[1][2], kh2[1][3]);
        }

        // independent online softmax (log2 domain)
        float rm1 = -1e30f, rm2 = -1e30f;
        #pragma unroll
        for (int t = 0; t < 4; t++) {
            rm1 = fmaxf(rm1, fmaxf(s[t][0], s[t][1]));
            rm2 = fmaxf(rm2, fmaxf(s[t][2], s[t][3]));
        }
        rm1 = fmaxf(rm1, __shfl_xor_sync(0xffffffffu, rm1, 1));
        rm1 = fmaxf(rm1, __shfl_xor_sync(0xffffffffu, rm1, 2));
        rm2 = fmaxf(rm2, __shfl_xor_sync(0xffffffffu, rm2, 1));
        rm2 = fmaxf(rm2, __shfl_xor_sync(0xffffffffu, rm2, 2));

        const float mn1 = fmaxf(m1, rm1), mn2 = fmaxf(m2, rm2);
        const float al1 = exp2f(m1 - mn1), al2 = exp2f(m2 - mn2);
        float sum1 = 0.f, sum2 = 0.f;
        #pragma unroll
        for (int t = 0; t < 4; t++) {
            const float2 e01 = exp2pair(s[t][0] - mn1, s[t][1] - mn1);
            const float2 e23 = exp2pair(s[t][2] - mn2, s[t][3] - mn2);
            s[t][0] = e01.x; s[t][1] = e01.y;
            s[t][2] = e23.x; s[t][3] = e23.y;
            sum1 += e01.x + e01.y;
            sum2 += e23.x + e23.y;
        }
        sum1 += __shfl_xor_sync(0xffffffffu, sum1, 1);
        sum1 += __shfl_xor_sync(0xffffffffu, sum1, 2);
        sum2 += __shfl_xor_sync(0xffffffffu, sum2, 1);
        sum2 += __shfl_xor_sync(0xffffffffu, sum2, 2);
        l1 = l1*al1 + sum1; l2 = l2*al2 + sum2;
        m1 = mn1; m2 = mn2;
        #pragma unroll
        for (int t = 0; t < 8; t++) {
            o[t][0] *= al1; o[t][1] *= al1;
            o[t][2] *= al2; o[t][3] *= al2;
        }

        // O += P @ V over this group's keys (2 k16 steps)
        #pragma unroll
        for (int kss = 0; kss < 2; kss++) {
            const int ks_g = wn*2 + kss;
            uint32_t ph[4], pl[4];
            split2(s[2*kss  ][0], s[2*kss  ][1], ph[0], pl[0]);
            split2(s[2*kss  ][2], s[2*kss  ][3], ph[1], pl[1]);
            split2(s[2*kss+1][0], s[2*kss+1][1], ph[2], pl[2]);
            split2(s[2*kss+1][2], s[2*kss+1][3], ph[3], pl[3]);
            const uint32_t vrow = (uint32_t)(ks_g*16) + vrow_b;
            #pragma unroll
            for (int np = 0; np < 4; np++) {
                const uint32_t vo = vrow*144 + (np*16 + vcol_b)*2;
                uint32_t h0,h1,h2,h3, l0,l1_,l2,l3;
                ldsm_x4t(h0, h1, h2, h3, buf + 2*AP_ + vo);
                ldsm_x4t(l0, l1_, l2, l3, buf + 3*AP_ + vo);
                mma_bf16(o[2*np  ], ph, h0, h1);
                mma_bf16(o[2*np+1], ph, h2, h3);
                mma_bf16(o[2*np  ], ph, l0, l1_);
                mma_bf16(o[2*np+1], ph, l2, l3);
                mma_bf16(o[2*np  ], pl, h0, h1);
                mma_bf16(o[2*np+1], pl, h2, h3);
            }
        }
    }

    // -------- final merge of the two independent key-half streams ----------
    __syncthreads();
    float* comb = (float*)smem;          // O: 64 rows x 66 floats
    float* cm   = comb + 64*66;          // m per row
    float* clv  = cm + 64;               // l per row
    const int rl  = wm*16 + (l >> 2);
    const int cl2 = (l & 3)*2;
    if (wn == 1) {
        if ((l & 3) == 0) {
            cm[rl]     = m1;  cm[rl+8]  = m2;
            clv[rl]    = l1;  clv[rl+8] = l2;
        }
        #pragma unroll
        for (int t = 0; t < 8; t++) {
            *(float2*)&comb[ rl     *66 + t*8 + cl2] = make_float2(o[t][0], o[t][1]);
            *(float2*)&comb[(rl + 8)*66 + t*8 + cl2] = make_float2(o[t][2], o[t][3]);
        }
    }
    __syncthreads();
    if (wn == 0) {
        const float mB1 = cm[rl], mB2 = cm[rl+8];
        const float lB1 = clv[rl], lB2 = clv[rl+8];
        const float mw1 = fmaxf(m1, mB1), mw2 = fmaxf(m2, mB2);
        const float fs1 = exp2f(m1 - mw1), fb1 = exp2f(mB1 - mw1);
        const float fs2 = exp2f(m2 - mw2), fb2 = exp2f(mB2 - mw2);
        const float i1 = 1.f / (l1*fs1 + lB1*fb1);
        const float i2 = 1.f / (l2*fs2 + lB2*fb2);
        const int b = bh >> 4, h = bh & 15;
        const int row1 = q0 + rl;
        #pragma unroll
        for (int t = 0; t < 8; t++) {
            const float2 p0 = *(const float2*)&comb[ rl     *66 + t*8 + cl2];
            const float2 p1 = *(const float2*)&comb[(rl + 8)*66 + t*8 + cl2];
            const int col = h*DK_ + t*8 + cl2;
            uint32_t hi, lo;
            size_t idx = (size_t)(b*S_ + row1)*DM_ + col;
            split2((o[t][0]*fs1 + p0.x*fb1)*i1, (o[t][1]*fs1 + p0.y*fb1)*i1, hi, lo);
            *(uint32_t*)(g_ch + idx) = hi;  *(uint32_t*)(g_cl + idx) = lo;
            idx = (size_t)(b*S_ + row1 + 8)*DM_ + col;
            split2((o[t][2]*fs2 + p1.x*fb2)*i2, (o[t][3]*fs2 + p1.y*fb2)*i2, hi, lo);
            *(uint32_t*)(g_ch + idx) = hi;  *(uint32_t*)(g_cl + idx) = lo;
        }
    }
}

// ===========================================================================
extern "C" void kernel_launch(void* const* d_in, const int* in_sizes, int n_in,
                              void* d_out, int out_size)
{
    (void)in_sizes; (void)n_in; (void)out_size;
    const float* query = (const float*)d_in[0];
    const float* key   = (const float*)d_in[1];
    const float* value = (const float*)d_in[2];
    const float* Wq    = (const float*)d_in[3];
    const float* bq    = (const float*)d_in[4];
    const float* Wk    = (const float*)d_in[5];
    const float* bk    = (const float*)d_in[6];
    const float* Wv    = (const float*)d_in[7];
    const float* bv    = (const float*)d_in[8];
    const float* Wo    = (const float*)d_in[9];
    const float* bo    = (const float*)d_in[10];
    float* out = (float*)d_out;

    __nv_bfloat16 *xqh,*xql,*xkh,*xkl,*xvh,*xvl;
    __nv_bfloat16 *wqh,*wql,*wkh,*wkl,*wvh,*wvl,*woh,*wol;
    __nv_bfloat16 *qh,*ql_,*kh,*kl,*vh,*vl,*ch,*cl;
    cudaGetSymbolAddress((void**)&xqh, g_xqh); cudaGetSymbolAddress((void**)&xql, g_xql);
    cudaGetSymbolAddress((void**)&xkh, g_xkh); cudaGetSymbolAddress((void**)&xkl, g_xkl);
    cudaGetSymbolAddress((void**)&xvh, g_xvh); cudaGetSymbolAddress((void**)&xvl, g_xvl);
    cudaGetSymbolAddress((void**)&wqh, g_wqh); cudaGetSymbolAddress((void**)&wql, g_wql);
    cudaGetSymbolAddress((void**)&wkh, g_wkh); cudaGetSymbolAddress((void**)&wkl, g_wkl);
    cudaGetSymbolAddress((void**)&wvh, g_wvh); cudaGetSymbolAddress((void**)&wvl, g_wvl);
    cudaGetSymbolAddress((void**)&woh, g_woh); cudaGetSymbolAddress((void**)&wol, g_wol);
    cudaGetSymbolAddress((void**)&qh, g_qh);   cudaGetSymbolAddress((void**)&ql_, g_ql);
    cudaGetSymbolAddress((void**)&kh, g_kh);   cudaGetSymbolAddress((void**)&kl, g_kl);
    cudaGetSymbolAddress((void**)&vh, g_vh);   cudaGetSymbolAddress((void**)&vl, g_vl);
    cudaGetSymbolAddress((void**)&ch, g_ch);   cudaGetSymbolAddress((void**)&cl, g_cl);

    cudaFuncSetAttribute(gemm_bf<true>,
                         cudaFuncAttributeMaxDynamicSharedMemorySize, GSMEM3);
    cudaFuncSetAttribute(gemm_bf<false>,
                         cudaFuncAttributeMaxDynamicSharedMemorySize, GSMEM3);
    cudaFuncSetAttribute(attn_mma_kernel,
                         cudaFuncAttributeMaxDynamicSharedMemorySize, ASMEM);

    const int nA4 = (int)(NA_/4), nW4 = (int)(NW_/4);

    Prep4 pi; pi.n4 = nA4;
    pi.x[0]=query; pi.h[0]=xqh; pi.l[0]=xql;
    pi.x[1]=key;   pi.h[1]=xkh; pi.l[1]=xkl;
    pi.x[2]=value; pi.h[2]=xvh; pi.l[2]=xvl;
    pi.x[3]=query; pi.h[3]=xqh; pi.l[3]=xql;   // unused
    prep_batch<<<dim3((nA4+255)/256, 3), 256>>>(pi);

    Prep4 pw; pw.n4 = nW4;
    pw.x[0]=Wq; pw.h[0]=wqh; pw.l[0]=wql;
    pw.x[1]=Wk; pw.h[1]=wkh; pw.l[1]=wkl;
    pw.x[2]=Wv; pw.h[2]=wvh; pw.l[2]=wvl;
    pw.x[3]=Wo; pw.h[3]=woh; pw.l[3]=wol;
    prep_batch<<<dim3((nW4+255)/256, 4), 256>>>(pw);

    // Q scale folds 1/sqrt(d_k) AND log2(e): scores land in log2 domain
    const float QSCALE = 0.125f * 1.4426950408889634f;

    GemmArgs3 gq;
    gq.g[0] = { xqh, xql, wqh, wql, bq, QSCALE, nullptr, qh,  ql_ };
    gq.g[1] = { xkh, xkl, wkh, wkl, bk, 1.0f,   nullptr, kh,  kl  };
    gq.g[2] = { xvh, xvl, wvh, wvl, bv, 1.0f,   nullptr, vh,  vl  };
    gemm_bf<true><<<dim3(M_/128, DM_/128, 3), 256, GSMEM3>>>(gq);

    attn_mma_kernel<<<dim3(S_/64, B_*H_), 256, ASMEM>>>();

    GemmArgs3 go;
    go.g[0] = { ch, cl, woh, wol, bo, 1.0f, out, nullptr, nullptr };
    go.g[1] = go.g[0];
    go.g[2] = go.g[0];
    gemm_bf<false><<<dim3(M_/128, DM_/128, 1), 256, GSMEM3>>>(go);
}

// round 13
// speedup vs baseline: 2.4257x; 2.2042x over previous
#include <cuda_runtime.h>
#include <cuda_fp16.h>
#include <cstdint>

#define B_   4
#define S_   2048
#define H_   16
#define DK_  64
#define DM_  1024
#define M_   (B_*S_)          // 8192
#define NA_  ((size_t)M_*DM_) // 8M elems
#define NW_  ((size_t)DM_*DM_)// 1M elems

// ---------------- scratch (__device__ globals; no allocs) ------------------
__device__ __half g_xq[NA_], g_xk[NA_], g_xv[NA_];
__device__ __half g_wq[NW_], g_wk[NW_], g_wv[NW_], g_wo[NW_];
__device__ __half g_q[NA_], g_k[NA_], g_v[NA_];   // head-split [b,h,s,d]
__device__ __half g_c[NA_];                        // merged ctx [b,s,h*d]

// ---------------- PTX helpers ----------------------------------------------
__device__ __forceinline__ uint32_t smem_u32(const void* p) {
    uint32_t a;
    asm("{ .reg .u64 t; cvta.to.shared.u64 t, %1; cvt.u32.u64 %0, t; }"
        : "=r"(a) : "l"(p));
    return a;
}
__device__ __forceinline__ void ldsm_x4(uint32_t& r0, uint32_t& r1,
                                        uint32_t& r2, uint32_t& r3, uint32_t a) {
    asm volatile("ldmatrix.sync.aligned.m8n8.x4.shared.b16 {%0,%1,%2,%3}, [%4];"
                 : "=r"(r0), "=r"(r1), "=r"(r2), "=r"(r3) : "r"(a));
}
__device__ __forceinline__ void ldsm_x4t(uint32_t& r0, uint32_t& r1,
                                         uint32_t& r2, uint32_t& r3, uint32_t a) {
    asm volatile("ldmatrix.sync.aligned.m8n8.x4.trans.shared.b16 {%0,%1,%2,%3}, [%4];"
                 : "=r"(r0), "=r"(r1), "=r"(r2), "=r"(r3) : "r"(a));
}
__device__ __forceinline__ void mma_f16(float* c, const uint32_t* a,
                                        uint32_t b0, uint32_t b1) {
    asm volatile("mma.sync.aligned.m16n8k16.row.col.f32.f16.f16.f32 "
                 "{%0,%1,%2,%3}, {%4,%5,%6,%7}, {%8,%9}, {%0,%1,%2,%3};"
                 : "+f"(c[0]), "+f"(c[1]), "+f"(c[2]), "+f"(c[3])
                 : "r"(a[0]), "r"(a[1]), "r"(a[2]), "r"(a[3]), "r"(b0), "r"(b1));
}
#define CP16(dst, src) \
    asm volatile("cp.async.cg.shared.global [%0], [%1], 16;" \
                 :: "r"(dst), "l"(src) : "memory")
#define CP_COMMIT() asm volatile("cp.async.commit_group;" ::: "memory")
#define CP_WAIT1()  asm volatile("cp.async.wait_group 1;"  ::: "memory")

__device__ __forceinline__ uint32_t pack_h2(float x, float y) {
    __half2 t = __floats2half2_rn(x, y);   // .x = low half
    return reinterpret_cast<uint32_t&>(t);
}
// exp2 of two values in one MUFU issue; returns floats AND the packed f16x2
__device__ __forceinline__ float2 exp2pairp(float a, float b, uint32_t& packed) {
    uint32_t p;
    asm("cvt.rn.f16x2.f32 %0, %1, %2;" : "=r"(p) : "f"(b), "f"(a)); // lo=a, hi=b
    asm("ex2.approx.f16x2 %0, %1;" : "=r"(packed) : "r"(p));
    const __half2 h = *reinterpret_cast<const __half2*>(&packed);
    return __half22float2(h);
}

// ---------------- prep: fp32 -> fp16 (batched up to 4) ----------------------
struct Prep4 { const float* x[4]; __half* o[4]; int n4; };

__global__ __launch_bounds__(256)
void prep_batch(Prep4 pa)
{
    const int z = blockIdx.y;
    const int i = blockIdx.x * 256 + threadIdx.x;
    if (i >= pa.n4) return;
    const float4 v = __ldg((const float4*)pa.x[z] + i);
    ((uint2*)pa.o[z])[i] = make_uint2(pack_h2(v.x, v.y), pack_h2(v.z, v.w));
}

// ===========================================================================
// GEMM: C[M,N] = A[M,K]*W[N,K]^T + bias   (single fp16 mma)
// CTA 128x128, K-tile 64, 3-stage cp.async ring (wait_group 1).
// 128B rows with SW128 swizzle (chunk ^= row&7). 96 KB smem, 2 CTAs/SM.
// ===========================================================================
#define GPF    (128*128)       // plane bytes 16384
#define GSTGF  (2*GPF)         // 32768
#define GSMEMF (3*GSTGF)       // 98304
#define GKTF   (DM_/64)        // 16

struct GemmArgs {
    const __half *A, *W;
    const float* bias;
    float scale;
    float* Cf;
    __half* Ch;
};
struct GemmArgs3 { GemmArgs g[3]; };

template<bool SPLITO>
__global__ __launch_bounds__(256, 2)
void gemm_f16(GemmArgs3 aa)
{
    const GemmArgs ga = aa.g[blockIdx.z];
    extern __shared__ char smem[];
    const uint32_t sb = smem_u32(smem);
    const int tid = threadIdx.x;
    const int w = tid >> 5, l = tid & 31;
    const int wm = w & 3, wn = w >> 2;
    const int m0 = blockIdx.x * 128;
    const int n0 = blockIdx.y * 128;

    const int srow = tid >> 2;          // 0..63
    const int sch  = tid & 3;           // chunks sch, sch+4
    const uint32_t s_swz = (uint32_t)(srow & 7);

    auto stage = [&](int kt, int s3) {
        const uint32_t buf = sb + (uint32_t)s3 * GSTGF;
        const int k0 = kt * 64;
        #pragma unroll
        for (int i = 0; i < 2; i++) {
            const int row = srow + i*64;
            #pragma unroll
            for (int c = 0; c < 2; c++) {
                const uint32_t ch = (uint32_t)(sch + c*4);
                const uint32_t off = (uint32_t)(row*128) + ((ch ^ s_swz) << 4);
                CP16(buf +       off, ga.A + (size_t)(m0+row)*DM_ + k0 + ch*8);
                CP16(buf + GPF + off, ga.W + (size_t)(n0+row)*DM_ + k0 + ch*8);
            }
        }
    };

    float acc[2][8][4];
    #pragma unroll
    for (int mt = 0; mt < 2; mt++)
        #pragma unroll
        for (int nt = 0; nt < 8; nt++)
            #pragma unroll
            for (int r = 0; r < 4; r++) acc[mt][nt][r] = 0.f;

    stage(0, 0); CP_COMMIT();
    stage(1, 1); CP_COMMIT();

    const uint32_t a_row = (uint32_t)(wm*32 + (l & 15));
    const uint32_t a_ch0 = (uint32_t)(l >> 4);
    const uint32_t a_swz = a_row & 7;
    const uint32_t b4row = (uint32_t)(wn*64 + ((l >> 4) & 1)*8 + (l & 7));
    const uint32_t b_ch0 = (uint32_t)((l >> 3) & 1);
    const uint32_t b_swz = b4row & 7;

    for (int kt = 0; kt < GKTF; kt++) {
        CP_WAIT1();
        __syncthreads();
        if (kt + 2 < GKTF) stage(kt+2, (kt+2)%3);
        CP_COMMIT();

        const uint32_t buf = sb + (uint32_t)((kt % 3) * GSTGF);
        #pragma unroll
        for (int ks = 0; ks < 4; ks++) {
            uint32_t ah[2][4];
            #pragma unroll
            for (int mt = 0; mt < 2; mt++) {
                const uint32_t ao = (a_row + mt*16)*128
                                  + (((ks*2 + a_ch0) ^ a_swz) << 4);
                ldsm_x4(ah[mt][0], ah[mt][1], ah[mt][2], ah[mt][3], buf + ao);
            }
            #pragma unroll
            for (int np = 0; np < 4; np++) {
                const uint32_t bo = (b4row + np*16)*128
                                  + (((ks*2 + b_ch0) ^ b_swz) << 4);
                uint32_t h0,h1,h2,h3;
                ldsm_x4(h0, h1, h2, h3, buf + GPF + bo);
                mma_f16(acc[0][2*np  ], ah[0], h0, h1);
                mma_f16(acc[1][2*np  ], ah[1], h0, h1);
                mma_f16(acc[0][2*np+1], ah[0], h2, h3);
                mma_f16(acc[1][2*np+1], ah[1], h2, h3);
            }
        }
    }

    // Epilogue
    #pragma unroll
    for (int mt = 0; mt < 2; mt++) {
        const int mrow = m0 + wm*32 + mt*16 + (l >> 2);
        #pragma unroll
        for (int nt = 0; nt < 8; nt++) {
            const int ncol = n0 + wn*64 + nt*8 + (l & 3)*2;
            const float2 bb = *(const float2*)(ga.bias + ncol);
            float2 o0 = { (acc[mt][nt][0] + bb.x)*ga.scale, (acc[mt][nt][1] + bb.y)*ga.scale };
            float2 o1 = { (acc[mt][nt][2] + bb.x)*ga.scale, (acc[mt][nt][3] + bb.y)*ga.scale };
            if (SPLITO) {
                const int h = ncol >> 6, d = ncol & 63;
                const int b0i = mrow >> 11, s0i = mrow & (S_-1);
                size_t idx = ((size_t)((b0i*H_ + h)*S_ + s0i))*DK_ + d;
                *(uint32_t*)(ga.Ch + idx) = pack_h2(o0.x, o0.y);
                const int m2 = mrow + 8;
                const int b1i = m2 >> 11, s1i = m2 & (S_-1);
                idx = ((size_t)((b1i*H_ + h)*S_ + s1i))*DK_ + d;
                *(uint32_t*)(ga.Ch + idx) = pack_h2(o1.x, o1.y);
            } else {
                *(float2*)(ga.Cf + (size_t)mrow*DM_ + ncol) = o0;
                *(float2*)(ga.Cf + (size_t)(mrow+8)*DM_ + ncol) = o1;
            }
        }
    }
}

// ===========================================================================
// Flash attention (fp16 single-term): 64-query CTA, 8 warps in 2 independent
// key-half groups (named barriers, drift freely). Scores in log2 domain;
// exp via ex2.approx.f16x2 whose PACKED output is used directly as the P
// fragments (no requantization). 3-stage cp.async ring. 2 CTAs/SM.
// ===========================================================================
#define APF   (64*144)        // plane bytes 9216 (K or V)
#define ASTGF (2*APF)         // 18432
#define ASMEMF (3*ASTGF)      // 55296
#define ANB   (S_/64)         // 32 key blocks

#define BAR_G(gid) \
    asm volatile("bar.sync %0, %1;" :: "r"((gid)+1), "r"(128) : "memory")

__global__ __launch_bounds__(256, 2)
void attn_mma_kernel()
{
    extern __shared__ char smem[];
    const uint32_t sb = smem_u32(smem);
    const int tid = threadIdx.x;
    const int w = tid >> 5, l = tid & 31;
    const int wm = w & 3, wn = w >> 2;        // wn = group id
    const int q0 = blockIdx.x * 64;
    const int bh = blockIdx.y;

    const __half* qp = g_q + (size_t)bh*S_*DK_;
    const __half* kp = g_k + (size_t)bh*S_*DK_;
    const __half* vp = g_v + (size_t)bh*S_*DK_;

    // group-local staging: this group's 32 key rows x 8 chunks x 2 planes
    const int gtid = tid & 127;
    const int srow = gtid >> 3;     // 0..15
    const int sch  = gtid & 7;

    auto stage = [&](int j, int s3) {
        const uint32_t buf = sb + (uint32_t)s3 * ASTGF;
        const int r0 = j*64 + wn*32;
        #pragma unroll
        for (int i = 0; i < 2; i++) {
            const int row = srow + i*16;              // 0..31 within half
            const uint32_t off = (uint32_t)((wn*32 + row)*144 + sch*16);
            const size_t g = (size_t)(r0 + row)*DK_ + sch*8;
            CP16(buf +       off, kp + g);
            CP16(buf + APF + off, vp + g);
        }
    };

    stage(0, 0); CP_COMMIT();
    stage(1, 1); CP_COMMIT();

    // Q fragments (pre-scaled by 0.125*log2e in projection)
    uint32_t qf[4][4];
    {
        const int r1 = q0 + wm*16 + (l >> 2);
        #pragma unroll
        for (int ks = 0; ks < 4; ks++) {
            #pragma unroll
            for (int rg = 0; rg < 4; rg++) {
                const int row = r1 + ((rg & 1) ? 8 : 0);
                const int col = ks*16 + (l & 3)*2 + ((rg & 2) ? 8 : 0);
                qf[ks][rg] = *(const uint32_t*)(qp + (size_t)row*DK_ + col);
            }
        }
    }

    float o[8][4];
    #pragma unroll
    for (int t = 0; t < 8; t++)
        #pragma unroll
        for (int r = 0; r < 4; r++) o[t][r] = 0.f;
    float m1 = -1e30f, m2 = -1e30f, l1 = 0.f, l2 = 0.f;

    const uint32_t kqrow = (uint32_t)(wn*32 + ((l >> 4) & 1)*8 + (l & 7));
    const uint32_t kb_kof = (uint32_t)(8 * ((l >> 3) & 1));
    const uint32_t vrow_b = (uint32_t)(((l >> 3) & 1)*8 + (l & 7));
    const uint32_t vcol_b = (uint32_t)(((l >> 4) & 1)*8);

    for (int j = 0; j < ANB; j++) {
        CP_WAIT1();
        BAR_G(wn);
        if (j + 2 < ANB) stage(j+2, (j+2)%3);
        CP_COMMIT();

        const uint32_t buf = sb + (uint32_t)((j % 3) * ASTGF);

        // S = Q K^T (log2 domain) over this group's 32 keys
        float s[4][4];
        #pragma unroll
        for (int t = 0; t < 4; t++)
            #pragma unroll
            for (int r = 0; r < 4; r++) s[t][r] = 0.f;

        #pragma unroll
        for (int ks = 0; ks < 4; ks++) {
            uint32_t kh[2][4];
            #pragma unroll
            for (int tp = 0; tp < 2; tp++) {
                const uint32_t bo = (kqrow + tp*16)*144 + (ks*16 + kb_kof)*2;
                ldsm_x4(kh[tp][0], kh[tp][1], kh[tp][2], kh[tp][3], buf + bo);
            }
            mma_f16(s[0], qf[ks], kh[0][0], kh[0][1]);
            mma_f16(s[1], qf[ks], kh[0][2], kh[0][3]);
            mma_f16(s[2], qf[ks], kh[1][0], kh[1][1]);
            mma_f16(s[3], qf[ks], kh[1][2], kh[1][3]);
        }

        // independent online softmax (log2 domain); keep packed f16 P frags
        float rm1 = -1e30f, rm2 = -1e30f;
        #pragma unroll
        for (int t = 0; t < 4; t++) {
            rm1 = fmaxf(rm1, fmaxf(s[t][0], s[t][1]));
            rm2 = fmaxf(rm2, fmaxf(s[t][2], s[t][3]));
        }
        rm1 = fmaxf(rm1, __shfl_xor_sync(0xffffffffu, rm1, 1));
        rm1 = fmaxf(rm1, __shfl_xor_sync(0xffffffffu, rm1, 2));
        rm2 = fmaxf(rm2, __shfl_xor_sync(0xffffffffu, rm2, 1));
        rm2 = fmaxf(rm2, __shfl_xor_sync(0xffffffffu, rm2, 2));

        const float mn1 = fmaxf(m1, rm1), mn2 = fmaxf(m2, rm2);
        const float al1 = exp2f(m1 - mn1), al2 = exp2f(m2 - mn2);
        float sum1 = 0.f, sum2 = 0.f;
        uint32_t u01[4], u23[4];
        #pragma unroll
        for (int t = 0; t < 4; t++) {
            const float2 e01 = exp2pairp(s[t][0] - mn1, s[t][1] - mn1, u01[t]);
            const float2 e23 = exp2pairp(s[t][2] - mn2, s[t][3] - mn2, u23[t]);
            sum1 += e01.x + e01.y;
            sum2 += e23.x + e23.y;
        }
        sum1 += __shfl_xor_sync(0xffffffffu, sum1, 1);
        sum1 += __shfl_xor_sync(0xffffffffu, sum1, 2);
        sum2 += __shfl_xor_sync(0xffffffffu, sum2, 1);
        sum2 += __shfl_xor_sync(0xffffffffu, sum2, 2);
        l1 = l1*al1 + sum1; l2 = l2*al2 + sum2;
        m1 = mn1; m2 = mn2;
        #pragma unroll
        for (int t = 0; t < 8; t++) {
            o[t][0] *= al1; o[t][1] *= al1;
            o[t][2] *= al2; o[t][3] *= al2;
        }

        // O += P @ V (P frags = packed ex2 output, no requantization)
        #pragma unroll
        for (int kss = 0; kss < 2; kss++) {
            const int ks_g = wn*2 + kss;
            const uint32_t pa[4] = { u01[2*kss], u23[2*kss],
                                     u01[2*kss+1], u23[2*kss+1] };
            const uint32_t vrow = (uint32_t)(ks_g*16) + vrow_b;
            #pragma unroll
            for (int np = 0; np < 4; np++) {
                const uint32_t vo = vrow*144 + (np*16 + vcol_b)*2;
                uint32_t v0,v1,v2,v3;
                ldsm_x4t(v0, v1, v2, v3, buf + APF + vo);
                mma_f16(o[2*np  ], pa, v0, v1);
                mma_f16(o[2*np+1], pa, v2, v3);
            }
        }
    }

    // -------- final merge of the two independent key-half streams ----------
    __syncthreads();
    float* comb = (float*)smem;          // O: 64 rows x 66 floats
    float* cm   = comb + 64*66;          // m per row
    float* clv  = cm + 64;               // l per row
    const int rl  = wm*16 + (l >> 2);
    const int cl2 = (l & 3)*2;
    if (wn == 1) {
        if ((l & 3) == 0) {
            cm[rl]     = m1;  cm[rl+8]  = m2;
            clv[rl]    = l1;  clv[rl+8] = l2;
        }
        #pragma unroll
        for (int t = 0; t < 8; t++) {
            *(float2*)&comb[ rl     *66 + t*8 + cl2] = make_float2(o[t][0], o[t][1]);
            *(float2*)&comb[(rl + 8)*66 + t*8 + cl2] = make_float2(o[t][2], o[t][3]);
        }
    }
    __syncthreads();
    if (wn == 0) {
        const float mB1 = cm[rl], mB2 = cm[rl+8];
        const float lB1 = clv[rl], lB2 = clv[rl+8];
        const float mw1 = fmaxf(m1, mB1), mw2 = fmaxf(m2, mB2);
        const float fs1 = exp2f(m1 - mw1), fb1 = exp2f(mB1 - mw1);
        const float fs2 = exp2f(m2 - mw2), fb2 = exp2f(mB2 - mw2);
        const float i1 = 1.f / (l1*fs1 + lB1*fb1);
        const float i2 = 1.f / (l2*fs2 + lB2*fb2);
        const int b = bh >> 4, h = bh & 15;
        const int row1 = q0 + rl;
        #pragma unroll
        for (int t = 0; t < 8; t++) {
            const float2 p0 = *(const float2*)&comb[ rl     *66 + t*8 + cl2];
            const float2 p1 = *(const float2*)&comb[(rl + 8)*66 + t*8 + cl2];
            const int col = h*DK_ + t*8 + cl2;
            size_t idx = (size_t)(b*S_ + row1)*DM_ + col;
            *(uint32_t*)(g_c + idx) =
                pack_h2((o[t][0]*fs1 + p0.x*fb1)*i1, (o[t][1]*fs1 + p0.y*fb1)*i1);
            idx = (size_t)(b*S_ + row1 + 8)*DM_ + col;
            *(uint32_t*)(g_c + idx) =
                pack_h2((o[t][2]*fs2 + p1.x*fb2)*i2, (o[t][3]*fs2 + p1.y*fb2)*i2);
        }
    }
}

// ===========================================================================
extern "C" void kernel_launch(void* const* d_in, const int* in_sizes, int n_in,
                              void* d_out, int out_size)
{
    (void)in_sizes; (void)n_in; (void)out_size;
    const float* query = (const float*)d_in[0];
    const float* key   = (const float*)d_in[1];
    const float* value = (const float*)d_in[2];
    const float* Wq    = (const float*)d_in[3];
    const float* bq    = (const float*)d_in[4];
    const float* Wk    = (const float*)d_in[5];
    const float* bk    = (const float*)d_in[6];
    const float* Wv    = (const float*)d_in[7];
    const float* bv    = (const float*)d_in[8];
    const float* Wo    = (const float*)d_in[9];
    const float* bo    = (const float*)d_in[10];
    float* out = (float*)d_out;

    __half *xq,*xk,*xv, *wq,*wk,*wv,*wo, *qh,*kh,*vh, *ch;
    cudaGetSymbolAddress((void**)&xq, g_xq);
    cudaGetSymbolAddress((void**)&xk, g_xk);
    cudaGetSymbolAddress((void**)&xv, g_xv);
    cudaGetSymbolAddress((void**)&wq, g_wq);
    cudaGetSymbolAddress((void**)&wk, g_wk);
    cudaGetSymbolAddress((void**)&wv, g_wv);
    cudaGetSymbolAddress((void**)&wo, g_wo);
    cudaGetSymbolAddress((void**)&qh, g_q);
    cudaGetSymbolAddress((void**)&kh, g_k);
    cudaGetSymbolAddress((void**)&vh, g_v);
    cudaGetSymbolAddress((void**)&ch, g_c);

    cudaFuncSetAttribute(gemm_f16<true>,
                         cudaFuncAttributeMaxDynamicSharedMemorySize, GSMEMF);
    cudaFuncSetAttribute(gemm_f16<false>,
                         cudaFuncAttributeMaxDynamicSharedMemorySize, GSMEMF);
    cudaFuncSetAttribute(attn_mma_kernel,
                         cudaFuncAttributeMaxDynamicSharedMemorySize, ASMEMF);

    const int nA4 = (int)(NA_/4), nW4 = (int)(NW_/4);

    Prep4 pi; pi.n4 = nA4;
    pi.x[0]=query; pi.o[0]=xq;
    pi.x[1]=key;   pi.o[1]=xk;
    pi.x[2]=value; pi.o[2]=xv;
    pi.x[3]=query; pi.o[3]=xq;   // unused
    prep_batch<<<dim3((nA4+255)/256, 3), 256>>>(pi);

    Prep4 pw; pw.n4 = nW4;
    pw.x[0]=Wq; pw.o[0]=wq;
    pw.x[1]=Wk; pw.o[1]=wk;
    pw.x[2]=Wv; pw.o[2]=wv;
    pw.x[3]=Wo; pw.o[3]=wo;
    prep_batch<<<dim3((nW4+255)/256, 4), 256>>>(pw);

    // Q scale folds 1/sqrt(d_k) AND log2(e): scores land in log2 domain
    const float QSCALE = 0.125f * 1.4426950408889634f;

    GemmArgs3 gq;
    gq.g[0] = { xq, wq, bq, QSCALE, nullptr, qh };
    gq.g[1] = { xk, wk, bk, 1.0f,   nullptr, kh };
    gq.g[2] = { xv, wv, bv, 1.0f,   nullptr, vh };
    gemm_f16<true><<<dim3(M_/128, DM_/128, 3), 256, GSMEMF>>>(gq);

    attn_mma_kernel<<<dim3(S_/64, B_*H_), 256, ASMEMF>>>();

    GemmArgs3 go;
    go.g[0] = { ch, wo, bo, 1.0f, out, nullptr };
    go.g[1] = go.g[0];
    go.g[2] = go.g[0];
    gemm_f16<false><<<dim3(M_/128, DM_/128, 1), 256, GSMEMF>>>(go);
}